// round 10
// baseline (speedup 1.0000x reference)
#include <cuda_runtime.h>
#include <cuda_bf16.h>
#include <mma.h>
#include <cstdint>

using namespace nvcuda;

// ---------------------------------------------------------------------------
// Problem shape
// ---------------------------------------------------------------------------
#define NROWS 8192
#define DIN   512
#define H1W   256
#define H2W   128
#define NSTEP 5
#define N1 (NSTEP*H1W)   // 1280
#define N2 (NSTEP*H2W)   // 640

#define KSTG  64
#define SLD   72                 // smem row stride in bf16 (144B)
#define TILEB (128*SLD*2)        // 18432 per 128x64 tile
#define STG   (2*TILEB)          // 36864 per stage (A+B)
#define GSM   (3*STG)            // 110592 — 2 CTAs/SM
#define CLD   129
// H2 variant: 64-row A tile
#define ATIL64 (64*SLD*2)        // 9216
#define STG64  (ATIL64+TILEB)    // 27648
#define GSM64  (3*STG64)         // 82944

// ---------------------------------------------------------------------------
// Scratch (device globals)
// ---------------------------------------------------------------------------
__device__ __nv_bfloat16 g_adjb[(size_t)NROWS*NROWS];
__device__ __nv_bfloat16 g_Xt  [(size_t)DIN*NROWS];      // X^T bf16
__device__ __nv_bfloat16 g_AX  [(size_t)NROWS*DIN];      // adj@X bf16
__device__ __nv_bfloat16 g_W1t [(size_t)NSTEP*H1W*DIN];  // [s][n][k]
__device__ __nv_bfloat16 g_W2t [(size_t)NSTEP*H2W*H1W];  // [s][n][k]
__device__ __nv_bfloat16 g_H1  [(size_t)NROWS*N1];       // relu(AX@W1) bf16
__device__ __nv_bfloat16 g_T2t [(size_t)N2*NROWS];       // (H1@W2)^T bf16
__device__ float         g_H2  [(size_t)NROWS*N2];       // relu(adj@T2) f32
__device__ __nv_bfloat16 g_abf [(size_t)NROWS*N2];       // centered a bf16
__device__ float         g_mean[N2];

// ---------------------------------------------------------------------------
// Helpers
// ---------------------------------------------------------------------------
static __device__ __forceinline__ void cp16(uint32_t sdst, const void* g) {
    asm volatile("cp.async.cg.shared.global [%0], [%1], 16;"
                 :: "r"(sdst), "l"(g) : "memory");
}
static __device__ __forceinline__ void cp_commit() {
    asm volatile("cp.async.commit_group;" ::: "memory");
}
template <int N>
static __device__ __forceinline__ void cp_wait() {
    asm volatile("cp.async.wait_group %0;" :: "n"(N) : "memory");
}
static __device__ __forceinline__ uint32_t smem_u32(const void* p) {
    uint32_t a;
    asm("{ .reg .u64 t; cvta.to.shared.u64 t, %1; cvt.u32.u64 %0, t; }"
        : "=r"(a) : "l"(p));
    return a;
}

// Stage an NRxKSTG bf16 tile (row stride SLD); NT = threads in CTA.
template <int NT, int NR>
static __device__ __forceinline__ void stage_t(uint32_t sdst,
                                               const __nv_bfloat16* __restrict__ src,
                                               long ld) {
    const int t = threadIdx.x;
    #pragma unroll
    for (int i = 0; i < NR * 8 / NT; i++) {
        int c = t + i * NT;
        int row = c >> 3, col = c & 7;
        cp16(sdst + row * (SLD * 2) + col * 16, src + (long)row * ld + col * 8);
    }
}

// 64x64 warp tile over one 64-K chunk
template <typename FragC>
static __device__ __forceinline__ void mma64(const __nv_bfloat16* As,
                                             const __nv_bfloat16* Bs,
                                             int wm, int wn, FragC (&cf)[4][4]) {
    #pragma unroll
    for (int kk = 0; kk < KSTG; kk += 16) {
        wmma::fragment<wmma::matrix_a, 16, 16, 16, __nv_bfloat16, wmma::row_major> af[4];
        wmma::fragment<wmma::matrix_b, 16, 16, 16, __nv_bfloat16, wmma::col_major> bf[4];
        #pragma unroll
        for (int i = 0; i < 4; i++)
            wmma::load_matrix_sync(af[i], As + (wm * 64 + i * 16) * SLD + kk, SLD);
        #pragma unroll
        for (int j = 0; j < 4; j++)
            wmma::load_matrix_sync(bf[j], Bs + (wn * 64 + j * 16) * SLD + kk, SLD);
        #pragma unroll
        for (int i = 0; i < 4; i++)
            #pragma unroll
            for (int j = 0; j < 4; j++)
                wmma::mma_sync(cf[i][j], af[i], bf[j], cf[i][j]);
    }
}

// 32x64 warp tile over one 64-K chunk
template <typename FragC>
static __device__ __forceinline__ void mma32(const __nv_bfloat16* As,
                                             const __nv_bfloat16* Bs,
                                             int wm, int wn, FragC (&cf)[2][4]) {
    #pragma unroll
    for (int kk = 0; kk < KSTG; kk += 16) {
        wmma::fragment<wmma::matrix_a, 16, 16, 16, __nv_bfloat16, wmma::row_major> af[2];
        wmma::fragment<wmma::matrix_b, 16, 16, 16, __nv_bfloat16, wmma::col_major> bf[4];
        #pragma unroll
        for (int i = 0; i < 2; i++)
            wmma::load_matrix_sync(af[i], As + (wm * 32 + i * 16) * SLD + kk, SLD);
        #pragma unroll
        for (int j = 0; j < 4; j++)
            wmma::load_matrix_sync(bf[j], Bs + (wn * 64 + j * 16) * SLD + kk, SLD);
        #pragma unroll
        for (int i = 0; i < 2; i++)
            #pragma unroll
            for (int j = 0; j < 4; j++)
                wmma::mma_sync(cf[i][j], af[i], bf[j], cf[i][j]);
    }
}

// ---------------------------------------------------------------------------
// 3-stage pipelined GEMM, single-sync mainloop (prefetch before compute).
// C[M,N] = op(A[M,K] @ B[N,K]^T). CTA 128x128, 4 warps, 64x64 warp tiles.
// EPI: 0 = bf16 transposed, 1 = bf16 row + relu, 2 = f32 row + relu,
//      3 = bf16 row (no relu)
// ---------------------------------------------------------------------------
template <int EPI>
__global__ void __launch_bounds__(128)
wgemm(const __nv_bfloat16* __restrict__ A, long lda, long aSlabCol,
      const __nv_bfloat16* __restrict__ B, long ldb, long bSlabStride, int outSlabN,
      char* __restrict__ Cv, long ldc, int K) {
    extern __shared__ char smem[];
    const uint32_t sb = smem_u32(smem);
    const int tid = threadIdx.x, warp = tid >> 5;
    const int wm = warp >> 1, wn = warp & 1;    // 2x2 warps, 64x64 each
    const int bx = blockIdx.x, by = blockIdx.y;

    const int slab = (bx * 128) / outSlabN;
    const __nv_bfloat16* Ab = A + (long)(by * 128) * lda + (long)slab * aSlabCol;
    const __nv_bfloat16* Bb = B + (long)slab * bSlabStride
                                + (long)((bx * 128) % outSlabN) * ldb;

    wmma::fragment<wmma::accumulator, 16, 16, 16, float> cf[4][4];
    #pragma unroll
    for (int i = 0; i < 4; i++)
        #pragma unroll
        for (int j = 0; j < 4; j++) wmma::fill_fragment(cf[i][j], 0.0f);

    const int KT = K >> 6;
    // prologue: stages 0, 1
    stage_t<128,128>(sb,         Ab,        lda);
    stage_t<128,128>(sb + TILEB, Bb,        ldb);
    cp_commit();
    stage_t<128,128>(sb + STG,         Ab + KSTG, lda);
    stage_t<128,128>(sb + STG + TILEB, Bb + KSTG, ldb);
    cp_commit();

    for (int t = 0; t < KT; t++) {
        cp_wait<1>();
        __syncthreads();          // all warps done with buffer (t+2)%3 (read at t-1)
        if (t + 2 < KT) {         // prefetch BEFORE compute for max overlap
            const uint32_t nb = sb + ((t + 2) % 3) * STG;
            stage_t<128,128>(nb,         Ab + (long)(t + 2) * KSTG, lda);
            stage_t<128,128>(nb + TILEB, Bb + (long)(t + 2) * KSTG, ldb);
        }
        cp_commit();              // uniform cadence (possibly empty)
        const char* buf = smem + (t % 3) * STG;
        mma64((const __nv_bfloat16*)buf,
              (const __nv_bfloat16*)(buf + TILEB), wm, wn, cf);
    }

    // ---- epilogue ----
    if (EPI == 2) {
        #pragma unroll
        for (int i = 0; i < 4; i++)
            #pragma unroll
            for (int j = 0; j < 4; j++) {
                #pragma unroll
                for (int e = 0; e < cf[i][j].num_elements; e++)
                    cf[i][j].x[e] = fmaxf(cf[i][j].x[e], 0.0f);
                float* Cp = (float*)Cv + (long)(by * 128 + wm * 64 + i * 16) * ldc
                                       + (long)bx * 128 + wn * 64 + j * 16;
                wmma::store_matrix_sync(Cp, cf[i][j], ldc, wmma::mem_row_major);
            }
        return;
    }

    // bf16 outputs via smem Cs[128][129] f32 (reuses stage buffers)
    __syncthreads();              // last-chunk readers must finish before overwrite
    float* Cs = (float*)smem;
    #pragma unroll
    for (int i = 0; i < 4; i++)
        #pragma unroll
        for (int j = 0; j < 4; j++)
            wmma::store_matrix_sync(Cs + (wm * 64 + i * 16) * CLD + wn * 64 + j * 16,
                                    cf[i][j], CLD, wmma::mem_row_major);
    __syncthreads();

    if (EPI == 0) {
        // transposed bf16: thread owns column n = tid, all 128 m values
        const int n = tid;
        __nv_bfloat16* dst = (__nv_bfloat16*)Cv + (long)(bx * 128 + n) * ldc
                                                + (long)by * 128;
        #pragma unroll
        for (int pass = 0; pass < 2; pass++) {
            uint32_t pk[32];
            #pragma unroll
            for (int k = 0; k < 32; k++) {
                int m = pass * 64 + 2 * k;
                __nv_bfloat162 h = __floats2bfloat162_rn(Cs[m * CLD + n],
                                                         Cs[(m + 1) * CLD + n]);
                pk[k] = *reinterpret_cast<uint32_t*>(&h);
            }
            #pragma unroll
            for (int i = 0; i < 8; i++)
                reinterpret_cast<uint4*>(dst + pass * 64)[i] =
                    *reinterpret_cast<uint4*>(pk + 4 * i);
        }
    } else {
        // row-major bf16: thread owns row m = tid (relu iff EPI==1)
        const int m = tid;
        __nv_bfloat16* dst = (__nv_bfloat16*)Cv + (long)(by * 128 + m) * ldc
                                                + (long)bx * 128;
        #pragma unroll
        for (int pass = 0; pass < 2; pass++) {
            uint32_t pk[32];
            #pragma unroll
            for (int k = 0; k < 32; k++) {
                int c = pass * 64 + 2 * k;
                float a = Cs[m * CLD + c];
                float b = Cs[m * CLD + c + 1];
                if (EPI == 1) { a = fmaxf(a, 0.0f); b = fmaxf(b, 0.0f); }
                __nv_bfloat162 h = __floats2bfloat162_rn(a, b);
                pk[k] = *reinterpret_cast<uint32_t*>(&h);
            }
            #pragma unroll
            for (int i = 0; i < 8; i++)
                reinterpret_cast<uint4*>(dst + pass * 64)[i] =
                    *reinterpret_cast<uint4*>(pk + 4 * i);
        }
    }
}

// ---------------------------------------------------------------------------
// H2 variant: CTA 64x128, 4 warps of 32x64, single-sync 3-stage pipeline,
// f32 row-major + relu output.
// ---------------------------------------------------------------------------
__global__ void __launch_bounds__(128)
wgemm64(const __nv_bfloat16* __restrict__ A, long lda,
        const __nv_bfloat16* __restrict__ B, long ldb,
        float* __restrict__ C, long ldc, int K) {
    extern __shared__ char smem[];
    const uint32_t sb = smem_u32(smem);
    const int tid = threadIdx.x, warp = tid >> 5;
    const int wm = warp >> 1, wn = warp & 1;    // 2x2 warps, 32x64 each
    const int bx = blockIdx.x, by = blockIdx.y;

    const __nv_bfloat16* Ab = A + (long)(by * 64) * lda;
    const __nv_bfloat16* Bb = B + (long)(bx * 128) * ldb;

    wmma::fragment<wmma::accumulator, 16, 16, 16, float> cf[2][4];
    #pragma unroll
    for (int i = 0; i < 2; i++)
        #pragma unroll
        for (int j = 0; j < 4; j++) wmma::fill_fragment(cf[i][j], 0.0f);

    const int KT = K >> 6;
    stage_t<128,64> (sb,          Ab,        lda);
    stage_t<128,128>(sb + ATIL64, Bb,        ldb);
    cp_commit();
    stage_t<128,64> (sb + STG64,          Ab + KSTG, lda);
    stage_t<128,128>(sb + STG64 + ATIL64, Bb + KSTG, ldb);
    cp_commit();

    for (int t = 0; t < KT; t++) {
        cp_wait<1>();
        __syncthreads();
        if (t + 2 < KT) {
            const uint32_t nb = sb + ((t + 2) % 3) * STG64;
            stage_t<128,64> (nb,          Ab + (long)(t + 2) * KSTG, lda);
            stage_t<128,128>(nb + ATIL64, Bb + (long)(t + 2) * KSTG, ldb);
        }
        cp_commit();
        const char* buf = smem + (t % 3) * STG64;
        mma32((const __nv_bfloat16*)buf,
              (const __nv_bfloat16*)(buf + ATIL64), wm, wn, cf);
    }

    #pragma unroll
    for (int i = 0; i < 2; i++)
        #pragma unroll
        for (int j = 0; j < 4; j++) {
            #pragma unroll
            for (int e = 0; e < cf[i][j].num_elements; e++)
                cf[i][j].x[e] = fmaxf(cf[i][j].x[e], 0.0f);
            float* Cp = C + (long)(by * 64 + wm * 32 + i * 16) * ldc
                          + (long)bx * 128 + wn * 64 + j * 16;
            wmma::store_matrix_sync(Cp, cf[i][j], ldc, wmma::mem_row_major);
        }
}

// ---------------------------------------------------------------------------
// Output kernel: triangular 1D grid (2080 CTAs), single-sync 3-buffer
// pipeline over 2*nact K-chunks. Sigmoid via 0.5-constant trick:
//   sigmoid(x) = 0.5 + x*q(x^2); Σ coef*0.5 added once at the end.
// ---------------------------------------------------------------------------
__global__ void __launch_bounds__(256)
wout(const __nv_bfloat16* __restrict__ a,
     const float* __restrict__ som, const float* __restrict__ cum,
     const int* __restrict__ tsp, const int* __restrict__ Tp,
     float* __restrict__ out) {
    // decode linear index -> upper-triangular (by <= bx), 64x64 tile grid
    const int li = blockIdx.x;
    double d = sqrt(129.0 * 129.0 - 8.0 * (double)li);
    int by = (int)((129.0 - d) * 0.5);
    while (by > 0 && by * (129 - by) / 2 > li) by--;
    while ((by + 1) * (129 - (by + 1)) / 2 <= li) by++;
    const int bx = by + li - by * (129 - by) / 2;

    extern __shared__ char smem[];
    const uint32_t sb = smem_u32(smem);
    const int tid = threadIdx.x, warp = tid >> 5;
    const int wm = warp >> 1, wn = warp & 1;
    const int ts = *tsp, T = *Tp;
    const int s0 = ts - 1, nch = 2 * (T - ts + 1);

    float sumCoef = 0.0f;
    for (int s = s0; s < T; s++) sumCoef += som[s];

    const __nv_bfloat16* Arow = a + (long)(by * 128) * N2;
    const __nv_bfloat16* Brow = a + (long)(bx * 128) * N2;

    wmma::fragment<wmma::accumulator, 16, 16, 16, float> of[2][4], cf[2][4];
    #pragma unroll
    for (int i = 0; i < 2; i++)
        #pragma unroll
        for (int j = 0; j < 4; j++) {
            wmma::fill_fragment(of[i][j], 0.0f);
            wmma::fill_fragment(cf[i][j], 0.0f);
        }

    {   // prologue: chunks 0,1 (step s0, halves 0/1)
        long o0 = (long)s0 * H2W;
        stage_t<256,128>(sb,         Arow + o0, N2);
        stage_t<256,128>(sb + TILEB, Brow + o0, N2);
        cp_commit();
        stage_t<256,128>(sb + STG,         Arow + o0 + KSTG, N2);
        stage_t<256,128>(sb + STG + TILEB, Brow + o0 + KSTG, N2);
        cp_commit();
    }

    for (int g = 0; g < nch; g++) {
        cp_wait<1>();
        __syncthreads();
        if (g + 2 < nch) {
            int gn = g + 2;
            long off = (long)(s0 + (gn >> 1)) * H2W + (gn & 1) * KSTG;
            uint32_t nb = sb + (gn % 3) * STG;
            stage_t<256,128>(nb,         Arow + off, N2);
            stage_t<256,128>(nb + TILEB, Brow + off, N2);
        }
        cp_commit();
        const char* buf = smem + (g % 3) * STG;
        mma32((const __nv_bfloat16*)buf,
              (const __nv_bfloat16*)(buf + TILEB), wm, wn, cf);
        if (g & 1) {   // step boundary: fold (sigmoid - 0.5), reset cf
            const float coef = som[s0 + (g >> 1)];
            #pragma unroll
            for (int i = 0; i < 2; i++)
                #pragma unroll
                for (int j = 0; j < 4; j++) {
                    #pragma unroll
                    for (int e = 0; e < cf[i][j].num_elements; e++) {
                        float x = cf[i][j].x[e];
                        float x2 = x * x;
                        float q = fmaf(x2, 0.00208333333f, -0.0208333333f);
                        q = fmaf(x2, q, 0.25f);
                        float t = x * q;                 // sigmoid(x) - 0.5 (poly)
                        if (fabsf(x) >= 0.25f)
                            t = __fdividef(1.0f, 1.0f + __expf(-x)) - 0.5f;
                        of[i][j].x[e] = fmaf(coef, t, of[i][j].x[e]);
                        cf[i][j].x[e] = 0.0f;
                    }
                }
        }
    }

    const float inv = __fdividef(1.0f, cum[ts - 1]);
    const float bias = 0.5f * sumCoef;
    #pragma unroll
    for (int i = 0; i < 2; i++)
        #pragma unroll
        for (int j = 0; j < 4; j++) {
            #pragma unroll
            for (int e = 0; e < of[i][j].num_elements; e++)
                of[i][j].x[e] = (of[i][j].x[e] + bias) * inv;
            const int mg = by * 128 + wm * 32 + i * 16;
            const int ng = bx * 128 + wn * 64 + j * 16;
            wmma::store_matrix_sync(out + (long)mg * NROWS + ng, of[i][j],
                                    NROWS, wmma::mem_row_major);
            if (bx != by)
                wmma::store_matrix_sync(out + (long)ng * NROWS + mg, of[i][j],
                                        NROWS, wmma::mem_col_major);
        }
}

// ---------------------------------------------------------------------------
// Pre/post-processing
// ---------------------------------------------------------------------------
__global__ void cvt_bf16_kernel(const float* __restrict__ src,
                                __nv_bfloat16* __restrict__ dst, long n8) {
    long i = (long)blockIdx.x * blockDim.x + threadIdx.x;
    long stride = (long)gridDim.x * blockDim.x;
    for (; i < n8; i += stride) {
        float4 va = reinterpret_cast<const float4*>(src)[2 * i];
        float4 vb = reinterpret_cast<const float4*>(src)[2 * i + 1];
        uint4 o;
        __nv_bfloat162 h0 = __floats2bfloat162_rn(va.x, va.y);
        __nv_bfloat162 h1 = __floats2bfloat162_rn(va.z, va.w);
        __nv_bfloat162 h2 = __floats2bfloat162_rn(vb.x, vb.y);
        __nv_bfloat162 h3 = __floats2bfloat162_rn(vb.z, vb.w);
        o.x = *reinterpret_cast<uint32_t*>(&h0);
        o.y = *reinterpret_cast<uint32_t*>(&h1);
        o.z = *reinterpret_cast<uint32_t*>(&h2);
        o.w = *reinterpret_cast<uint32_t*>(&h3);
        reinterpret_cast<uint4*>(dst)[i] = o;
    }
}
// Transpose X^T (single big slab): Wt[n][k] = W[k][n] bf16
__global__ void transpose_w_kernel(const float* __restrict__ W,
                                   __nv_bfloat16* __restrict__ Wt, int K, int N) {
    for (long idx = blockIdx.x * blockDim.x + threadIdx.x; idx < (long)K * N;
         idx += (long)gridDim.x * blockDim.x) {
        long n = idx / K, k = idx % K;
        Wt[n * K + k] = __float2bfloat16(W[k * N + n]);
    }
}
// Merged W1/W2 slab transposes (y<NSTEP: W1 slab y; else W2 slab y-NSTEP)
__global__ void transpose_w2_kernel(const float* __restrict__ W1,
                                    const float* __restrict__ W2,
                                    __nv_bfloat16* __restrict__ W1t,
                                    __nv_bfloat16* __restrict__ W2t) {
    const int y = blockIdx.y;
    const float* Ws; __nv_bfloat16* Wd; int K, N;
    if (y < NSTEP) { Ws = W1 + (long)y * DIN * H1W; Wd = W1t + (long)y * DIN * H1W;
                     K = DIN; N = H1W; }
    else           { Ws = W2 + (long)(y - NSTEP) * H1W * H2W;
                     Wd = W2t + (long)(y - NSTEP) * H1W * H2W; K = H1W; N = H2W; }
    for (long idx = blockIdx.x * blockDim.x + threadIdx.x; idx < (long)K * N;
         idx += (long)gridDim.x * blockDim.x) {
        long n = idx / K, k = idx % K;
        Wd[n * K + k] = __float2bfloat16(Ws[k * N + n]);
    }
}
__global__ void mean_kernel(const float* __restrict__ H2, float* __restrict__ mean) {
    const int tx = threadIdx.x & 31;
    const int ty = threadIdx.x >> 5;
    const int col = blockIdx.x * 32 + tx;
    float s = 0.0f;
    for (int r = ty; r < NROWS; r += 8)
        s += H2[(long)r * N2 + col];
    __shared__ float red[8][32];
    red[ty][tx] = s;
    __syncthreads();
    if (ty == 0) {
        float t = 0.0f;
        #pragma unroll
        for (int i = 0; i < 8; i++) t += red[i][tx];
        mean[col] = t * (1.0f / NROWS);
    }
}
__global__ void center_kernel(const float* __restrict__ H2,
                              const float* __restrict__ mean,
                              __nv_bfloat16* __restrict__ a, long n) {
    long i = (long)blockIdx.x * blockDim.x + threadIdx.x;
    long st = (long)gridDim.x * blockDim.x;
    for (; i < n; i += st) {
        int c = (int)(i % N2);
        a[i] = __float2bfloat16(H2[i] - mean[c]);
    }
}

// ---------------------------------------------------------------------------
// Launch
// ---------------------------------------------------------------------------
extern "C" void kernel_launch(void* const* d_in, const int* in_sizes, int n_in,
                              void* d_out, int out_size) {
    const float* X   = (const float*)d_in[0];
    const float* adj = (const float*)d_in[1];
    const float* W1  = (const float*)d_in[2];
    const float* W2  = (const float*)d_in[3];
    const float* cum = (const float*)d_in[4];
    const float* som = (const float*)d_in[5];
    const int*   tsp = (const int*)d_in[6];
    const int*   Tp  = (const int*)d_in[7];
    float* out = (float*)d_out;
    (void)in_sizes; (void)n_in; (void)out_size;

    void *p_adjb, *p_xt, *p_ax, *p_w1t, *p_w2t, *p_h1, *p_t2t, *p_h2, *p_abf, *p_mean;
    cudaGetSymbolAddress(&p_adjb, g_adjb);
    cudaGetSymbolAddress(&p_xt,   g_Xt);
    cudaGetSymbolAddress(&p_ax,   g_AX);
    cudaGetSymbolAddress(&p_w1t,  g_W1t);
    cudaGetSymbolAddress(&p_w2t,  g_W2t);
    cudaGetSymbolAddress(&p_h1,   g_H1);
    cudaGetSymbolAddress(&p_t2t,  g_T2t);
    cudaGetSymbolAddress(&p_h2,   g_H2);
    cudaGetSymbolAddress(&p_abf,  g_abf);
    cudaGetSymbolAddress(&p_mean, g_mean);

    cudaFuncSetAttribute(wgemm<0>, cudaFuncAttributeMaxDynamicSharedMemorySize, GSM);
    cudaFuncSetAttribute(wgemm<1>, cudaFuncAttributeMaxDynamicSharedMemorySize, GSM);
    cudaFuncSetAttribute(wgemm<3>, cudaFuncAttributeMaxDynamicSharedMemorySize, GSM);
    cudaFuncSetAttribute(wgemm64,  cudaFuncAttributeMaxDynamicSharedMemorySize, GSM64);
    cudaFuncSetAttribute(wout,     cudaFuncAttributeMaxDynamicSharedMemorySize, GSM);

    // (1) adj -> bf16, (2) X^T, (3) merged W transposes, (4) AX ← profiled slot
    cvt_bf16_kernel<<<4096, 256>>>(adj, (__nv_bfloat16*)p_adjb, (long)NROWS * NROWS / 8);
    transpose_w_kernel<<<2048, 256>>>(X, (__nv_bfloat16*)p_xt, NROWS, DIN);
    transpose_w2_kernel<<<dim3(48, 2 * NSTEP), 256>>>(
        W1 + (size_t)DIN * H1W, W2 + (size_t)H1W * H2W,
        (__nv_bfloat16*)p_w1t, (__nv_bfloat16*)p_w2t);

    // AX = adj @ X                 [8192 x 512] bf16 (no relu)
    wgemm<3><<<dim3(DIN/128, NROWS/128), 128, GSM>>>(
        (const __nv_bfloat16*)p_adjb, NROWS, 0,
        (const __nv_bfloat16*)p_xt, NROWS, 0, DIN,
        (char*)p_ax, DIN, NROWS);

    // H1 = relu(AX @ W1slab)       [8192 x 1280] bf16
    wgemm<1><<<dim3(N1/128, NROWS/128), 128, GSM>>>(
        (const __nv_bfloat16*)p_ax, DIN, 0,
        (const __nv_bfloat16*)p_w1t, DIN, (long)H1W * DIN, H1W,
        (char*)p_h1, N1, DIN);

    // T2t = (H1slab @ W2slab)^T    [640 x 8192] bf16
    wgemm<0><<<dim3(N2/128, NROWS/128), 128, GSM>>>(
        (const __nv_bfloat16*)p_h1, N1, H1W,
        (const __nv_bfloat16*)p_w2t, H1W, (long)H2W * H1W, H2W,
        (char*)p_t2t, NROWS, H1W);

    // H2 = relu(adj @ T2)          [8192 x 640] f32 — 64-row tiles
    wgemm64<<<dim3(N2/128, NROWS/64), 128, GSM64>>>(
        (const __nv_bfloat16*)p_adjb, NROWS,
        (const __nv_bfloat16*)p_t2t, NROWS,
        (float*)p_h2, N2, NROWS);

    mean_kernel<<<N2 / 32, 256>>>((const float*)p_h2, (float*)p_mean);
    center_kernel<<<4096, 256>>>((const float*)p_h2, (const float*)p_mean,
                                 (__nv_bfloat16*)p_abf, (long)NROWS * N2);

    // triangular grid: 64*65/2 = 2080 CTAs
    wout<<<2080, 256, GSM>>>(
        (const __nv_bfloat16*)p_abf, som, cum, tsp, Tp, out);
}

// round 11
// speedup vs baseline: 1.0078x; 1.0078x over previous
#include <cuda_runtime.h>
#include <cuda_bf16.h>
#include <mma.h>
#include <cstdint>

using namespace nvcuda;

// ---------------------------------------------------------------------------
// Problem shape
// ---------------------------------------------------------------------------
#define NROWS 8192
#define DIN   512
#define H1W   256
#define H2W   128
#define NSTEP 5
#define N1 (NSTEP*H1W)   // 1280
#define N2 (NSTEP*H2W)   // 640

#define KSTG  64
#define SLD   72                 // smem row stride in bf16 (144B)
#define TILEB (128*SLD*2)        // 18432 per 128x64 tile
#define STG   (2*TILEB)          // 36864 per stage (A+B)
#define GSM   (3*STG)            // 110592 — 2 CTAs/SM
#define CLD   129
// 64-row-A variant (AX + H2)
#define ATIL64 (64*SLD*2)        // 9216
#define STG64  (ATIL64+TILEB)    // 27648
#define GSM64  (3*STG64)         // 82944
#define CLD64  129

// ---------------------------------------------------------------------------
// Scratch (device globals)
// ---------------------------------------------------------------------------
__device__ __nv_bfloat16 g_adjb[(size_t)NROWS*NROWS];
__device__ __nv_bfloat16 g_Xt  [(size_t)DIN*NROWS];      // X^T bf16
__device__ __nv_bfloat16 g_AX  [(size_t)NROWS*DIN];      // adj@X bf16
__device__ __nv_bfloat16 g_W1t [(size_t)NSTEP*H1W*DIN];  // [s][n][k]
__device__ __nv_bfloat16 g_W2t [(size_t)NSTEP*H2W*H1W];  // [s][n][k]
__device__ __nv_bfloat16 g_H1  [(size_t)NROWS*N1];       // relu(AX@W1) bf16
__device__ __nv_bfloat16 g_T2t [(size_t)N2*NROWS];       // (H1@W2)^T bf16
__device__ float         g_H2  [(size_t)NROWS*N2];       // relu(adj@T2) f32
__device__ __nv_bfloat16 g_abf [(size_t)NROWS*N2];       // centered a bf16
__device__ float         g_mean[N2];

// ---------------------------------------------------------------------------
// Helpers
// ---------------------------------------------------------------------------
static __device__ __forceinline__ void cp16(uint32_t sdst, const void* g) {
    asm volatile("cp.async.cg.shared.global [%0], [%1], 16;"
                 :: "r"(sdst), "l"(g) : "memory");
}
static __device__ __forceinline__ void cp_commit() {
    asm volatile("cp.async.commit_group;" ::: "memory");
}
template <int N>
static __device__ __forceinline__ void cp_wait() {
    asm volatile("cp.async.wait_group %0;" :: "n"(N) : "memory");
}
static __device__ __forceinline__ uint32_t smem_u32(const void* p) {
    uint32_t a;
    asm("{ .reg .u64 t; cvta.to.shared.u64 t, %1; cvt.u32.u64 %0, t; }"
        : "=r"(a) : "l"(p));
    return a;
}
// Poly for |x|<0.25 (abs err < 2e-8), per-element exact fallback otherwise.
static __device__ __forceinline__ float fast_sigmoid(float x) {
    float ax = fabsf(x);
    float x2 = x * x;
    float p = 0.5f + x * (0.25f + x2 * (-0.0208333333f + x2 * 0.00208333333f));
    if (ax >= 0.25f) p = __fdividef(1.0f, 1.0f + __expf(-x));
    return p;
}

// Stage an NRxKSTG bf16 tile (row stride SLD); NT = threads in CTA.
template <int NT, int NR>
static __device__ __forceinline__ void stage_t(uint32_t sdst,
                                               const __nv_bfloat16* __restrict__ src,
                                               long ld) {
    const int t = threadIdx.x;
    #pragma unroll
    for (int i = 0; i < NR * 8 / NT; i++) {
        int c = t + i * NT;
        int row = c >> 3, col = c & 7;
        cp16(sdst + row * (SLD * 2) + col * 16, src + (long)row * ld + col * 8);
    }
}

// 64x64 warp tile over one 64-K chunk
template <typename FragC>
static __device__ __forceinline__ void mma64(const __nv_bfloat16* As,
                                             const __nv_bfloat16* Bs,
                                             int wm, int wn, FragC (&cf)[4][4]) {
    #pragma unroll
    for (int kk = 0; kk < KSTG; kk += 16) {
        wmma::fragment<wmma::matrix_a, 16, 16, 16, __nv_bfloat16, wmma::row_major> af[4];
        wmma::fragment<wmma::matrix_b, 16, 16, 16, __nv_bfloat16, wmma::col_major> bf[4];
        #pragma unroll
        for (int i = 0; i < 4; i++)
            wmma::load_matrix_sync(af[i], As + (wm * 64 + i * 16) * SLD + kk, SLD);
        #pragma unroll
        for (int j = 0; j < 4; j++)
            wmma::load_matrix_sync(bf[j], Bs + (wn * 64 + j * 16) * SLD + kk, SLD);
        #pragma unroll
        for (int i = 0; i < 4; i++)
            #pragma unroll
            for (int j = 0; j < 4; j++)
                wmma::mma_sync(cf[i][j], af[i], bf[j], cf[i][j]);
    }
}

// 32x64 warp tile over one 64-K chunk
template <typename FragC>
static __device__ __forceinline__ void mma32(const __nv_bfloat16* As,
                                             const __nv_bfloat16* Bs,
                                             int wm, int wn, FragC (&cf)[2][4]) {
    #pragma unroll
    for (int kk = 0; kk < KSTG; kk += 16) {
        wmma::fragment<wmma::matrix_a, 16, 16, 16, __nv_bfloat16, wmma::row_major> af[2];
        wmma::fragment<wmma::matrix_b, 16, 16, 16, __nv_bfloat16, wmma::col_major> bf[4];
        #pragma unroll
        for (int i = 0; i < 2; i++)
            wmma::load_matrix_sync(af[i], As + (wm * 32 + i * 16) * SLD + kk, SLD);
        #pragma unroll
        for (int j = 0; j < 4; j++)
            wmma::load_matrix_sync(bf[j], Bs + (wn * 64 + j * 16) * SLD + kk, SLD);
        #pragma unroll
        for (int i = 0; i < 2; i++)
            #pragma unroll
            for (int j = 0; j < 4; j++)
                wmma::mma_sync(cf[i][j], af[i], bf[j], cf[i][j]);
    }
}

// ---------------------------------------------------------------------------
// 3-stage pipelined GEMM (two-sync R9 schedule): C = op(A[M,K] @ B[N,K]^T).
// CTA 128x128, 4 warps, 64x64 warp tiles.
// EPI: 0 = bf16 transposed, 1 = bf16 row + relu
// ---------------------------------------------------------------------------
template <int EPI>
__global__ void __launch_bounds__(128)
wgemm(const __nv_bfloat16* __restrict__ A, long lda, long aSlabCol,
      const __nv_bfloat16* __restrict__ B, long ldb, long bSlabStride, int outSlabN,
      char* __restrict__ Cv, long ldc, int K) {
    extern __shared__ char smem[];
    const uint32_t sb = smem_u32(smem);
    const int tid = threadIdx.x, warp = tid >> 5;
    const int wm = warp >> 1, wn = warp & 1;    // 2x2 warps, 64x64 each
    const int bx = blockIdx.x, by = blockIdx.y;

    const int slab = (bx * 128) / outSlabN;
    const __nv_bfloat16* Ab = A + (long)(by * 128) * lda + (long)slab * aSlabCol;
    const __nv_bfloat16* Bb = B + (long)slab * bSlabStride
                                + (long)((bx * 128) % outSlabN) * ldb;

    wmma::fragment<wmma::accumulator, 16, 16, 16, float> cf[4][4];
    #pragma unroll
    for (int i = 0; i < 4; i++)
        #pragma unroll
        for (int j = 0; j < 4; j++) wmma::fill_fragment(cf[i][j], 0.0f);

    const int KT = K >> 6;
    // prologue: stages 0, 1
    stage_t<128,128>(sb,         Ab,        lda);
    stage_t<128,128>(sb + TILEB, Bb,        ldb);
    cp_commit();
    stage_t<128,128>(sb + STG,         Ab + KSTG, lda);
    stage_t<128,128>(sb + STG + TILEB, Bb + KSTG, ldb);
    cp_commit();

    for (int t = 0; t < KT; t++) {
        cp_wait<1>();
        __syncthreads();
        const char* buf = smem + (t % 3) * STG;
        mma64((const __nv_bfloat16*)buf,
              (const __nv_bfloat16*)(buf + TILEB), wm, wn, cf);
        __syncthreads();
        if (t + 2 < KT) {
            const uint32_t nb = sb + ((t + 2) % 3) * STG;
            stage_t<128,128>(nb,         Ab + (long)(t + 2) * KSTG, lda);
            stage_t<128,128>(nb + TILEB, Bb + (long)(t + 2) * KSTG, ldb);
        }
        cp_commit();   // uniform cadence
    }

    // bf16 outputs via smem Cs[128][129] f32 (reuses stage buffers)
    float* Cs = (float*)smem;
    #pragma unroll
    for (int i = 0; i < 4; i++)
        #pragma unroll
        for (int j = 0; j < 4; j++)
            wmma::store_matrix_sync(Cs + (wm * 64 + i * 16) * CLD + wn * 64 + j * 16,
                                    cf[i][j], CLD, wmma::mem_row_major);
    __syncthreads();

    if (EPI == 0) {
        // transposed bf16: thread owns column n = tid, all 128 m values
        const int n = tid;
        __nv_bfloat16* dst = (__nv_bfloat16*)Cv + (long)(bx * 128 + n) * ldc
                                                + (long)by * 128;
        #pragma unroll
        for (int pass = 0; pass < 2; pass++) {
            uint32_t pk[32];
            #pragma unroll
            for (int k = 0; k < 32; k++) {
                int m = pass * 64 + 2 * k;
                __nv_bfloat162 h = __floats2bfloat162_rn(Cs[m * CLD + n],
                                                         Cs[(m + 1) * CLD + n]);
                pk[k] = *reinterpret_cast<uint32_t*>(&h);
            }
            #pragma unroll
            for (int i = 0; i < 8; i++)
                reinterpret_cast<uint4*>(dst + pass * 64)[i] =
                    *reinterpret_cast<uint4*>(pk + 4 * i);
        }
    } else {
        // row-major bf16 + relu: thread owns row m = tid
        const int m = tid;
        __nv_bfloat16* dst = (__nv_bfloat16*)Cv + (long)(by * 128 + m) * ldc
                                                + (long)bx * 128;
        #pragma unroll
        for (int pass = 0; pass < 2; pass++) {
            uint32_t pk[32];
            #pragma unroll
            for (int k = 0; k < 32; k++) {
                int c = pass * 64 + 2 * k;
                float a = fmaxf(Cs[m * CLD + c],     0.0f);
                float b = fmaxf(Cs[m * CLD + c + 1], 0.0f);
                __nv_bfloat162 h = __floats2bfloat162_rn(a, b);
                pk[k] = *reinterpret_cast<uint32_t*>(&h);
            }
            #pragma unroll
            for (int i = 0; i < 8; i++)
                reinterpret_cast<uint4*>(dst + pass * 64)[i] =
                    *reinterpret_cast<uint4*>(pk + 4 * i);
        }
    }
}

// ---------------------------------------------------------------------------
// 64-row-A variant: CTA 64x128, 4 warps of 32x64, two-sync 3-stage pipeline.
// EPI: 2 = f32 row-major + relu (H2), 3 = bf16 row-major no relu (AX)
// ---------------------------------------------------------------------------
template <int EPI>
__global__ void __launch_bounds__(128)
wgemm64(const __nv_bfloat16* __restrict__ A, long lda,
        const __nv_bfloat16* __restrict__ B, long ldb,
        char* __restrict__ Cv, long ldc, int K) {
    extern __shared__ char smem[];
    const uint32_t sb = smem_u32(smem);
    const int tid = threadIdx.x, warp = tid >> 5;
    const int wm = warp >> 1, wn = warp & 1;    // 2x2 warps, 32x64 each
    const int bx = blockIdx.x, by = blockIdx.y;

    const __nv_bfloat16* Ab = A + (long)(by * 64) * lda;
    const __nv_bfloat16* Bb = B + (long)(bx * 128) * ldb;

    wmma::fragment<wmma::accumulator, 16, 16, 16, float> cf[2][4];
    #pragma unroll
    for (int i = 0; i < 2; i++)
        #pragma unroll
        for (int j = 0; j < 4; j++) wmma::fill_fragment(cf[i][j], 0.0f);

    const int KT = K >> 6;
    stage_t<128,64> (sb,          Ab,        lda);
    stage_t<128,128>(sb + ATIL64, Bb,        ldb);
    cp_commit();
    stage_t<128,64> (sb + STG64,          Ab + KSTG, lda);
    stage_t<128,128>(sb + STG64 + ATIL64, Bb + KSTG, ldb);
    cp_commit();

    for (int t = 0; t < KT; t++) {
        cp_wait<1>();
        __syncthreads();
        const char* buf = smem + (t % 3) * STG64;
        mma32((const __nv_bfloat16*)buf,
              (const __nv_bfloat16*)(buf + ATIL64), wm, wn, cf);
        __syncthreads();
        if (t + 2 < KT) {
            const uint32_t nb = sb + ((t + 2) % 3) * STG64;
            stage_t<128,64> (nb,          Ab + (long)(t + 2) * KSTG, lda);
            stage_t<128,128>(nb + ATIL64, Bb + (long)(t + 2) * KSTG, ldb);
        }
        cp_commit();
    }

    if (EPI == 2) {
        #pragma unroll
        for (int i = 0; i < 2; i++)
            #pragma unroll
            for (int j = 0; j < 4; j++) {
                #pragma unroll
                for (int e = 0; e < cf[i][j].num_elements; e++)
                    cf[i][j].x[e] = fmaxf(cf[i][j].x[e], 0.0f);
                float* Cp = (float*)Cv + (long)(by * 64 + wm * 32 + i * 16) * ldc
                                       + (long)bx * 128 + wn * 64 + j * 16;
                wmma::store_matrix_sync(Cp, cf[i][j], ldc, wmma::mem_row_major);
            }
        return;
    }

    // EPI == 3: bf16 row-major, no relu, via smem Cs[64][129] f32
    __syncthreads();     // other warps may still read last stage buffer
    float* Cs = (float*)smem;
    #pragma unroll
    for (int i = 0; i < 2; i++)
        #pragma unroll
        for (int j = 0; j < 4; j++)
            wmma::store_matrix_sync(Cs + (wm * 32 + i * 16) * CLD64 + wn * 64 + j * 16,
                                    cf[i][j], CLD64, wmma::mem_row_major);
    __syncthreads();

    const int m = tid >> 1, nb0 = (tid & 1) * 64;
    uint32_t pk[32];
    #pragma unroll
    for (int k = 0; k < 32; k++) {
        __nv_bfloat162 h = __floats2bfloat162_rn(Cs[m * CLD64 + nb0 + 2*k],
                                                 Cs[m * CLD64 + nb0 + 2*k + 1]);
        pk[k] = *reinterpret_cast<uint32_t*>(&h);
    }
    __nv_bfloat16* dst = (__nv_bfloat16*)Cv + (long)(by * 64 + m) * ldc
                                            + (long)bx * 128 + nb0;
    #pragma unroll
    for (int i = 0; i < 8; i++)
        reinterpret_cast<uint4*>(dst)[i] = *reinterpret_cast<uint4*>(pk + 4 * i);
}

// ---------------------------------------------------------------------------
// Output kernel (R9 version, unchanged): symmetric (bx>=by), two-sync
// 3-buffer pipeline, 8 warps of 32x64, sigmoid fold, mirrored stores.
// ---------------------------------------------------------------------------
__global__ void __launch_bounds__(256)
wout(const __nv_bfloat16* __restrict__ a,
     const float* __restrict__ som, const float* __restrict__ cum,
     const int* __restrict__ tsp, const int* __restrict__ Tp,
     float* __restrict__ out) {
    const int bx = blockIdx.x, by = blockIdx.y;
    if (bx < by) return;
    extern __shared__ char smem[];
    const uint32_t sb = smem_u32(smem);
    const int tid = threadIdx.x, warp = tid >> 5;
    const int wm = warp >> 1, wn = warp & 1;
    const int ts = *tsp, T = *Tp;
    const int s0 = ts - 1, nch = 2 * (T - ts + 1);

    const __nv_bfloat16* Arow = a + (long)(by * 128) * N2;
    const __nv_bfloat16* Brow = a + (long)(bx * 128) * N2;

    wmma::fragment<wmma::accumulator, 16, 16, 16, float> of[2][4], cf[2][4];
    #pragma unroll
    for (int i = 0; i < 2; i++)
        #pragma unroll
        for (int j = 0; j < 4; j++) {
            wmma::fill_fragment(of[i][j], 0.0f);
            wmma::fill_fragment(cf[i][j], 0.0f);
        }

    {   // prologue: chunks 0,1 (step s0, halves 0/1)
        long o0 = (long)s0 * H2W;
        stage_t<256,128>(sb,         Arow + o0, N2);
        stage_t<256,128>(sb + TILEB, Brow + o0, N2);
        cp_commit();
        stage_t<256,128>(sb + STG,         Arow + o0 + KSTG, N2);
        stage_t<256,128>(sb + STG + TILEB, Brow + o0 + KSTG, N2);
        cp_commit();
    }

    for (int g = 0; g < nch; g++) {
        cp_wait<1>();
        __syncthreads();
        const char* buf = smem + (g % 3) * STG;
        mma32((const __nv_bfloat16*)buf,
              (const __nv_bfloat16*)(buf + TILEB), wm, wn, cf);
        __syncthreads();
        if (g + 2 < nch) {
            int gn = g + 2;
            long off = (long)(s0 + (gn >> 1)) * H2W + (gn & 1) * KSTG;
            uint32_t nb = sb + (gn % 3) * STG;
            stage_t<256,128>(nb,         Arow + off, N2);
            stage_t<256,128>(nb + TILEB, Brow + off, N2);
        }
        cp_commit();
        if (g & 1) {   // step boundary: fold sigmoid, reset cf
            const float coef = som[s0 + (g >> 1)];
            #pragma unroll
            for (int i = 0; i < 2; i++)
                #pragma unroll
                for (int j = 0; j < 4; j++) {
                    #pragma unroll
                    for (int e = 0; e < cf[i][j].num_elements; e++) {
                        of[i][j].x[e] += coef * fast_sigmoid(cf[i][j].x[e]);
                        cf[i][j].x[e] = 0.0f;
                    }
                }
        }
    }

    const float inv = __fdividef(1.0f, cum[ts - 1]);
    #pragma unroll
    for (int i = 0; i < 2; i++)
        #pragma unroll
        for (int j = 0; j < 4; j++) {
            #pragma unroll
            for (int e = 0; e < of[i][j].num_elements; e++)
                of[i][j].x[e] *= inv;
            const int mg = by * 128 + wm * 32 + i * 16;
            const int ng = bx * 128 + wn * 64 + j * 16;
            wmma::store_matrix_sync(out + (long)mg * NROWS + ng, of[i][j],
                                    NROWS, wmma::mem_row_major);
            if (bx != by)
                wmma::store_matrix_sync(out + (long)ng * NROWS + mg, of[i][j],
                                        NROWS, wmma::mem_col_major);
        }
}

// ---------------------------------------------------------------------------
// Pre/post-processing
// ---------------------------------------------------------------------------
__global__ void cvt_bf16_kernel(const float* __restrict__ src,
                                __nv_bfloat16* __restrict__ dst, long n8) {
    long i = (long)blockIdx.x * blockDim.x + threadIdx.x;
    long stride = (long)gridDim.x * blockDim.x;
    for (; i < n8; i += stride) {
        float4 va = reinterpret_cast<const float4*>(src)[2 * i];
        float4 vb = reinterpret_cast<const float4*>(src)[2 * i + 1];
        uint4 o;
        __nv_bfloat162 h0 = __floats2bfloat162_rn(va.x, va.y);
        __nv_bfloat162 h1 = __floats2bfloat162_rn(va.z, va.w);
        __nv_bfloat162 h2 = __floats2bfloat162_rn(vb.x, vb.y);
        __nv_bfloat162 h3 = __floats2bfloat162_rn(vb.z, vb.w);
        o.x = *reinterpret_cast<uint32_t*>(&h0);
        o.y = *reinterpret_cast<uint32_t*>(&h1);
        o.z = *reinterpret_cast<uint32_t*>(&h2);
        o.w = *reinterpret_cast<uint32_t*>(&h3);
        reinterpret_cast<uint4*>(dst)[i] = o;
    }
}
// Transpose X^T (single big slab): Wt[n][k] = W[k][n] bf16
__global__ void transpose_w_kernel(const float* __restrict__ W,
                                   __nv_bfloat16* __restrict__ Wt, int K, int N) {
    for (long idx = blockIdx.x * blockDim.x + threadIdx.x; idx < (long)K * N;
         idx += (long)gridDim.x * blockDim.x) {
        long n = idx / K, k = idx % K;
        Wt[n * K + k] = __float2bfloat16(W[k * N + n]);
    }
}
// Merged W1/W2 slab transposes (y<NSTEP: W1 slab y; else W2 slab y-NSTEP)
__global__ void transpose_w2_kernel(const float* __restrict__ W1,
                                    const float* __restrict__ W2,
                                    __nv_bfloat16* __restrict__ W1t,
                                    __nv_bfloat16* __restrict__ W2t) {
    const int y = blockIdx.y;
    const float* Ws; __nv_bfloat16* Wd; int K, N;
    if (y < NSTEP) { Ws = W1 + (long)y * DIN * H1W; Wd = W1t + (long)y * DIN * H1W;
                     K = DIN; N = H1W; }
    else           { Ws = W2 + (long)(y - NSTEP) * H1W * H2W;
                     Wd = W2t + (long)(y - NSTEP) * H1W * H2W; K = H1W; N = H2W; }
    for (long idx = blockIdx.x * blockDim.x + threadIdx.x; idx < (long)K * N;
         idx += (long)gridDim.x * blockDim.x) {
        long n = idx / K, k = idx % K;
        Wd[n * K + k] = __float2bfloat16(Ws[k * N + n]);
    }
}
__global__ void mean_kernel(const float* __restrict__ H2, float* __restrict__ mean) {
    const int tx = threadIdx.x & 31;
    const int ty = threadIdx.x >> 5;
    const int col = blockIdx.x * 32 + tx;
    float s = 0.0f;
    for (int r = ty; r < NROWS; r += 8)
        s += H2[(long)r * N2 + col];
    __shared__ float red[8][32];
    red[ty][tx] = s;
    __syncthreads();
    if (ty == 0) {
        float t = 0.0f;
        #pragma unroll
        for (int i = 0; i < 8; i++) t += red[i][tx];
        mean[col] = t * (1.0f / NROWS);
    }
}
__global__ void center_kernel(const float* __restrict__ H2,
                              const float* __restrict__ mean,
                              __nv_bfloat16* __restrict__ a, long n) {
    long i = (long)blockIdx.x * blockDim.x + threadIdx.x;
    long st = (long)gridDim.x * blockDim.x;
    for (; i < n; i += st) {
        int c = (int)(i % N2);
        a[i] = __float2bfloat16(H2[i] - mean[c]);
    }
}

// ---------------------------------------------------------------------------
// Launch
// ---------------------------------------------------------------------------
extern "C" void kernel_launch(void* const* d_in, const int* in_sizes, int n_in,
                              void* d_out, int out_size) {
    const float* X   = (const float*)d_in[0];
    const float* adj = (const float*)d_in[1];
    const float* W1  = (const float*)d_in[2];
    const float* W2  = (const float*)d_in[3];
    const float* cum = (const float*)d_in[4];
    const float* som = (const float*)d_in[5];
    const int*   tsp = (const int*)d_in[6];
    const int*   Tp  = (const int*)d_in[7];
    float* out = (float*)d_out;
    (void)in_sizes; (void)n_in; (void)out_size;

    void *p_adjb, *p_xt, *p_ax, *p_w1t, *p_w2t, *p_h1, *p_t2t, *p_h2, *p_abf, *p_mean;
    cudaGetSymbolAddress(&p_adjb, g_adjb);
    cudaGetSymbolAddress(&p_xt,   g_Xt);
    cudaGetSymbolAddress(&p_ax,   g_AX);
    cudaGetSymbolAddress(&p_w1t,  g_W1t);
    cudaGetSymbolAddress(&p_w2t,  g_W2t);
    cudaGetSymbolAddress(&p_h1,   g_H1);
    cudaGetSymbolAddress(&p_t2t,  g_T2t);
    cudaGetSymbolAddress(&p_h2,   g_H2);
    cudaGetSymbolAddress(&p_abf,  g_abf);
    cudaGetSymbolAddress(&p_mean, g_mean);

    cudaFuncSetAttribute(wgemm<0>,   cudaFuncAttributeMaxDynamicSharedMemorySize, GSM);
    cudaFuncSetAttribute(wgemm<1>,   cudaFuncAttributeMaxDynamicSharedMemorySize, GSM);
    cudaFuncSetAttribute(wgemm64<2>, cudaFuncAttributeMaxDynamicSharedMemorySize, GSM64);
    cudaFuncSetAttribute(wgemm64<3>, cudaFuncAttributeMaxDynamicSharedMemorySize, GSM64);
    cudaFuncSetAttribute(wout,       cudaFuncAttributeMaxDynamicSharedMemorySize, GSM);

    // (1) adj -> bf16, (2) X^T, (3) merged W transposes, (4) AX ← profiled slot
    cvt_bf16_kernel<<<4096, 256>>>(adj, (__nv_bfloat16*)p_adjb, (long)NROWS * NROWS / 8);
    transpose_w_kernel<<<2048, 256>>>(X, (__nv_bfloat16*)p_xt, NROWS, DIN);
    transpose_w2_kernel<<<dim3(48, 2 * NSTEP), 256>>>(
        W1 + (size_t)DIN * H1W, W2 + (size_t)H1W * H2W,
        (__nv_bfloat16*)p_w1t, (__nv_bfloat16*)p_w2t);

    // AX = adj @ X   [8192 x 512] bf16 — 64-row tiles: 512 CTAs (tail balance)
    wgemm64<3><<<dim3(DIN/128, NROWS/64), 128, GSM64>>>(
        (const __nv_bfloat16*)p_adjb, NROWS,
        (const __nv_bfloat16*)p_xt, NROWS,
        (char*)p_ax, DIN, NROWS);

    // H1 = relu(AX @ W1slab)       [8192 x 1280] bf16
    wgemm<1><<<dim3(N1/128, NROWS/128), 128, GSM>>>(
        (const __nv_bfloat16*)p_ax, DIN, 0,
        (const __nv_bfloat16*)p_w1t, DIN, (long)H1W * DIN, H1W,
        (char*)p_h1, N1, DIN);

    // T2t = (H1slab @ W2slab)^T    [640 x 8192] bf16
    wgemm<0><<<dim3(N2/128, NROWS/128), 128, GSM>>>(
        (const __nv_bfloat16*)p_h1, N1, H1W,
        (const __nv_bfloat16*)p_w2t, H1W, (long)H2W * H1W, H2W,
        (char*)p_t2t, NROWS, H1W);

    // H2 = relu(adj @ T2)          [8192 x 640] f32 — 64-row tiles
    wgemm64<2><<<dim3(N2/128, NROWS/64), 128, GSM64>>>(
        (const __nv_bfloat16*)p_adjb, NROWS,
        (const __nv_bfloat16*)p_t2t, NROWS,
        (char*)p_h2, N2, NROWS);

    mean_kernel<<<N2 / 32, 256>>>((const float*)p_h2, (float*)p_mean);
    center_kernel<<<4096, 256>>>((const float*)p_h2, (const float*)p_mean,
                                 (__nv_bfloat16*)p_abf, (long)NROWS * N2);

    wout<<<dim3(NROWS/128, NROWS/128), 256, GSM>>>(
        (const __nv_bfloat16*)p_abf, som, cum, tsp, Tp, out);
}

// round 12
// speedup vs baseline: 1.0170x; 1.0092x over previous
#include <cuda_runtime.h>
#include <cuda_bf16.h>
#include <mma.h>
#include <cstdint>

using namespace nvcuda;

// ---------------------------------------------------------------------------
// Problem shape
// ---------------------------------------------------------------------------
#define NROWS 8192
#define DIN   512
#define H1W   256
#define H2W   128
#define NSTEP 5
#define N1 (NSTEP*H1W)   // 1280
#define N2 (NSTEP*H2W)   // 640

#define KSTG  64
#define SLD   72                 // smem row stride in bf16 (144B)
#define TILEB (128*SLD*2)        // 18432 per 128x64 tile
#define STG   (2*TILEB)          // 36864 per stage (A+B)
#define GSM   (3*STG)            // 110592 — 2 CTAs/SM
#define CLD   129
// H2 variant: 64-row A tile
#define ATIL64 (64*SLD*2)        // 9216
#define STG64  (ATIL64+TILEB)    // 27648
#define GSM64  (3*STG64)         // 82944

// ---------------------------------------------------------------------------
// Scratch (device globals)
// ---------------------------------------------------------------------------
__device__ __nv_bfloat16 g_adjb[(size_t)NROWS*NROWS];
__device__ __nv_bfloat16 g_Xt  [(size_t)DIN*NROWS];      // X^T bf16
__device__ __nv_bfloat16 g_AX  [(size_t)NROWS*DIN];      // adj@X bf16
__device__ __nv_bfloat16 g_W1t [(size_t)NSTEP*H1W*DIN];  // [s][n][k]
__device__ __nv_bfloat16 g_W2t [(size_t)NSTEP*H2W*H1W];  // [s][n][k]
__device__ __nv_bfloat16 g_H1  [(size_t)NROWS*N1];       // relu(AX@W1) bf16
__device__ __nv_bfloat16 g_T2t [(size_t)N2*NROWS];       // (H1@W2)^T bf16
__device__ float         g_H2  [(size_t)NROWS*N2];       // relu(adj@T2) f32
__device__ __nv_bfloat16 g_abf [(size_t)NROWS*N2];       // centered a bf16
__device__ float         g_mean[N2];

// ---------------------------------------------------------------------------
// Helpers
// ---------------------------------------------------------------------------
static __device__ __forceinline__ void cp16(uint32_t sdst, const void* g) {
    asm volatile("cp.async.cg.shared.global [%0], [%1], 16;"
                 :: "r"(sdst), "l"(g) : "memory");
}
static __device__ __forceinline__ void cp_commit() {
    asm volatile("cp.async.commit_group;" ::: "memory");
}
template <int N>
static __device__ __forceinline__ void cp_wait() {
    asm volatile("cp.async.wait_group %0;" :: "n"(N) : "memory");
}
static __device__ __forceinline__ uint32_t smem_u32(const void* p) {
    uint32_t a;
    asm("{ .reg .u64 t; cvta.to.shared.u64 t, %1; cvt.u32.u64 %0, t; }"
        : "=r"(a) : "l"(p));
    return a;
}

// Stage an NRxKSTG bf16 tile (row stride SLD); NT = threads in CTA.
template <int NT, int NR>
static __device__ __forceinline__ void stage_t(uint32_t sdst,
                                               const __nv_bfloat16* __restrict__ src,
                                               long ld) {
    const int t = threadIdx.x;
    #pragma unroll
    for (int i = 0; i < NR * 8 / NT; i++) {
        int c = t + i * NT;
        int row = c >> 3, col = c & 7;
        cp16(sdst + row * (SLD * 2) + col * 16, src + (long)row * ld + col * 8);
    }
}

// 64x64 warp tile over one 64-K chunk
template <typename FragC>
static __device__ __forceinline__ void mma64(const __nv_bfloat16* As,
                                             const __nv_bfloat16* Bs,
                                             int wm, int wn, FragC (&cf)[4][4]) {
    #pragma unroll
    for (int kk = 0; kk < KSTG; kk += 16) {
        wmma::fragment<wmma::matrix_a, 16, 16, 16, __nv_bfloat16, wmma::row_major> af[4];
        wmma::fragment<wmma::matrix_b, 16, 16, 16, __nv_bfloat16, wmma::col_major> bf[4];
        #pragma unroll
        for (int i = 0; i < 4; i++)
            wmma::load_matrix_sync(af[i], As + (wm * 64 + i * 16) * SLD + kk, SLD);
        #pragma unroll
        for (int j = 0; j < 4; j++)
            wmma::load_matrix_sync(bf[j], Bs + (wn * 64 + j * 16) * SLD + kk, SLD);
        #pragma unroll
        for (int i = 0; i < 4; i++)
            #pragma unroll
            for (int j = 0; j < 4; j++)
                wmma::mma_sync(cf[i][j], af[i], bf[j], cf[i][j]);
    }
}

// 32x64 warp tile over one 64-K chunk
template <typename FragC>
static __device__ __forceinline__ void mma32(const __nv_bfloat16* As,
                                             const __nv_bfloat16* Bs,
                                             int wm, int wn, FragC (&cf)[2][4]) {
    #pragma unroll
    for (int kk = 0; kk < KSTG; kk += 16) {
        wmma::fragment<wmma::matrix_a, 16, 16, 16, __nv_bfloat16, wmma::row_major> af[2];
        wmma::fragment<wmma::matrix_b, 16, 16, 16, __nv_bfloat16, wmma::col_major> bf[4];
        #pragma unroll
        for (int i = 0; i < 2; i++)
            wmma::load_matrix_sync(af[i], As + (wm * 32 + i * 16) * SLD + kk, SLD);
        #pragma unroll
        for (int j = 0; j < 4; j++)
            wmma::load_matrix_sync(bf[j], Bs + (wn * 64 + j * 16) * SLD + kk, SLD);
        #pragma unroll
        for (int i = 0; i < 2; i++)
            #pragma unroll
            for (int j = 0; j < 4; j++)
                wmma::mma_sync(cf[i][j], af[i], bf[j], cf[i][j]);
    }
}

// ---------------------------------------------------------------------------
// 3-stage pipelined GEMM (two-sync schedule): C = op(A[M,K] @ B[N,K]^T).
// CTA 128x128, 4 warps, 64x64 warp tiles.
// EPI: 0 = bf16 transposed, 1 = bf16 row + relu, 3 = bf16 row (no relu)
// ---------------------------------------------------------------------------
template <int EPI>
__global__ void __launch_bounds__(128)
wgemm(const __nv_bfloat16* __restrict__ A, long lda, long aSlabCol,
      const __nv_bfloat16* __restrict__ B, long ldb, long bSlabStride, int outSlabN,
      char* __restrict__ Cv, long ldc, int K) {
    extern __shared__ char smem[];
    const uint32_t sb = smem_u32(smem);
    const int tid = threadIdx.x, warp = tid >> 5;
    const int wm = warp >> 1, wn = warp & 1;    // 2x2 warps, 64x64 each
    const int bx = blockIdx.x, by = blockIdx.y;

    const int slab = (bx * 128) / outSlabN;
    const __nv_bfloat16* Ab = A + (long)(by * 128) * lda + (long)slab * aSlabCol;
    const __nv_bfloat16* Bb = B + (long)slab * bSlabStride
                                + (long)((bx * 128) % outSlabN) * ldb;

    wmma::fragment<wmma::accumulator, 16, 16, 16, float> cf[4][4];
    #pragma unroll
    for (int i = 0; i < 4; i++)
        #pragma unroll
        for (int j = 0; j < 4; j++) wmma::fill_fragment(cf[i][j], 0.0f);

    const int KT = K >> 6;
    // prologue: stages 0, 1
    stage_t<128,128>(sb,         Ab,        lda);
    stage_t<128,128>(sb + TILEB, Bb,        ldb);
    cp_commit();
    stage_t<128,128>(sb + STG,         Ab + KSTG, lda);
    stage_t<128,128>(sb + STG + TILEB, Bb + KSTG, ldb);
    cp_commit();

    for (int t = 0; t < KT; t++) {
        cp_wait<1>();
        __syncthreads();
        const char* buf = smem + (t % 3) * STG;
        mma64((const __nv_bfloat16*)buf,
              (const __nv_bfloat16*)(buf + TILEB), wm, wn, cf);
        __syncthreads();
        if (t + 2 < KT) {
            const uint32_t nb = sb + ((t + 2) % 3) * STG;
            stage_t<128,128>(nb,         Ab + (long)(t + 2) * KSTG, lda);
            stage_t<128,128>(nb + TILEB, Bb + (long)(t + 2) * KSTG, ldb);
        }
        cp_commit();   // uniform cadence
    }

    // bf16 outputs via smem Cs[128][129] f32 (reuses stage buffers)
    float* Cs = (float*)smem;
    #pragma unroll
    for (int i = 0; i < 4; i++)
        #pragma unroll
        for (int j = 0; j < 4; j++)
            wmma::store_matrix_sync(Cs + (wm * 64 + i * 16) * CLD + wn * 64 + j * 16,
                                    cf[i][j], CLD, wmma::mem_row_major);
    __syncthreads();

    if (EPI == 0) {
        // transposed bf16: thread owns column n = tid, all 128 m values
        const int n = tid;
        __nv_bfloat16* dst = (__nv_bfloat16*)Cv + (long)(bx * 128 + n) * ldc
                                                + (long)by * 128;
        #pragma unroll
        for (int pass = 0; pass < 2; pass++) {
            uint32_t pk[32];
            #pragma unroll
            for (int k = 0; k < 32; k++) {
                int m = pass * 64 + 2 * k;
                __nv_bfloat162 h = __floats2bfloat162_rn(Cs[m * CLD + n],
                                                         Cs[(m + 1) * CLD + n]);
                pk[k] = *reinterpret_cast<uint32_t*>(&h);
            }
            #pragma unroll
            for (int i = 0; i < 8; i++)
                reinterpret_cast<uint4*>(dst + pass * 64)[i] =
                    *reinterpret_cast<uint4*>(pk + 4 * i);
        }
    } else {
        // row-major bf16: thread owns row m = tid (relu iff EPI==1)
        const int m = tid;
        __nv_bfloat16* dst = (__nv_bfloat16*)Cv + (long)(by * 128 + m) * ldc
                                                + (long)bx * 128;
        #pragma unroll
        for (int pass = 0; pass < 2; pass++) {
            uint32_t pk[32];
            #pragma unroll
            for (int k = 0; k < 32; k++) {
                int c = pass * 64 + 2 * k;
                float a = Cs[m * CLD + c];
                float b = Cs[m * CLD + c + 1];
                if (EPI == 1) { a = fmaxf(a, 0.0f); b = fmaxf(b, 0.0f); }
                __nv_bfloat162 h = __floats2bfloat162_rn(a, b);
                pk[k] = *reinterpret_cast<uint32_t*>(&h);
            }
            #pragma unroll
            for (int i = 0; i < 8; i++)
                reinterpret_cast<uint4*>(dst + pass * 64)[i] =
                    *reinterpret_cast<uint4*>(pk + 4 * i);
        }
    }
}

// ---------------------------------------------------------------------------
// H2 variant: CTA 64x128, 4 warps of 32x64, two-sync 3-stage pipeline,
// f32 row-major + relu output. (Kept from R9 — tail fix for K=8192 GEMM.)
// ---------------------------------------------------------------------------
__global__ void __launch_bounds__(128)
wgemm64(const __nv_bfloat16* __restrict__ A, long lda,
        const __nv_bfloat16* __restrict__ B, long ldb,
        float* __restrict__ C, long ldc, int K) {
    extern __shared__ char smem[];
    const uint32_t sb = smem_u32(smem);
    const int tid = threadIdx.x, warp = tid >> 5;
    const int wm = warp >> 1, wn = warp & 1;    // 2x2 warps, 32x64 each
    const int bx = blockIdx.x, by = blockIdx.y;

    const __nv_bfloat16* Ab = A + (long)(by * 64) * lda;
    const __nv_bfloat16* Bb = B + (long)(bx * 128) * ldb;

    wmma::fragment<wmma::accumulator, 16, 16, 16, float> cf[2][4];
    #pragma unroll
    for (int i = 0; i < 2; i++)
        #pragma unroll
        for (int j = 0; j < 4; j++) wmma::fill_fragment(cf[i][j], 0.0f);

    const int KT = K >> 6;
    stage_t<128,64> (sb,          Ab,        lda);
    stage_t<128,128>(sb + ATIL64, Bb,        ldb);
    cp_commit();
    stage_t<128,64> (sb + STG64,          Ab + KSTG, lda);
    stage_t<128,128>(sb + STG64 + ATIL64, Bb + KSTG, ldb);
    cp_commit();

    for (int t = 0; t < KT; t++) {
        cp_wait<1>();
        __syncthreads();
        const char* buf = smem + (t % 3) * STG64;
        mma32((const __nv_bfloat16*)buf,
              (const __nv_bfloat16*)(buf + ATIL64), wm, wn, cf);
        __syncthreads();
        if (t + 2 < KT) {
            const uint32_t nb = sb + ((t + 2) % 3) * STG64;
            stage_t<128,64> (nb,          Ab + (long)(t + 2) * KSTG, lda);
            stage_t<128,128>(nb + ATIL64, Bb + (long)(t + 2) * KSTG, ldb);
        }
        cp_commit();
    }

    #pragma unroll
    for (int i = 0; i < 2; i++)
        #pragma unroll
        for (int j = 0; j < 4; j++) {
            #pragma unroll
            for (int e = 0; e < cf[i][j].num_elements; e++)
                cf[i][j].x[e] = fmaxf(cf[i][j].x[e], 0.0f);
            float* Cp = C + (long)(by * 64 + wm * 32 + i * 16) * ldc
                          + (long)bx * 128 + wn * 64 + j * 16;
            wmma::store_matrix_sync(Cp, cf[i][j], ldc, wmma::mem_row_major);
        }
}

// ---------------------------------------------------------------------------
// Output kernel: triangular 1D grid (2080 CTAs), two-sync 3-buffer pipeline,
// 8 warps of 32x64. Sigmoid 0.5-bias trick:
//   sigmoid(x) = 0.5 + x*q(x^2); Σ coef*0.5 added once in the epilogue.
// ---------------------------------------------------------------------------
__global__ void __launch_bounds__(256)
wout(const __nv_bfloat16* __restrict__ a,
     const float* __restrict__ som, const float* __restrict__ cum,
     const int* __restrict__ tsp, const int* __restrict__ Tp,
     float* __restrict__ out) {
    // decode linear index -> upper-triangular (by <= bx), 64x64 tile grid
    const int li = blockIdx.x;
    double d = sqrt(129.0 * 129.0 - 8.0 * (double)li);
    int by = (int)((129.0 - d) * 0.5);
    while (by > 0 && by * (129 - by) / 2 > li) by--;
    while ((by + 1) * (129 - (by + 1)) / 2 <= li) by++;
    const int bx = by + li - by * (129 - by) / 2;

    extern __shared__ char smem[];
    const uint32_t sb = smem_u32(smem);
    const int tid = threadIdx.x, warp = tid >> 5;
    const int wm = warp >> 1, wn = warp & 1;
    const int ts = *tsp, T = *Tp;
    const int s0 = ts - 1, nch = 2 * (T - ts + 1);

    float sumCoef = 0.0f;
    for (int s = s0; s < T; s++) sumCoef += som[s];

    const __nv_bfloat16* Arow = a + (long)(by * 128) * N2;
    const __nv_bfloat16* Brow = a + (long)(bx * 128) * N2;

    wmma::fragment<wmma::accumulator, 16, 16, 16, float> of[2][4], cf[2][4];
    #pragma unroll
    for (int i = 0; i < 2; i++)
        #pragma unroll
        for (int j = 0; j < 4; j++) {
            wmma::fill_fragment(of[i][j], 0.0f);
            wmma::fill_fragment(cf[i][j], 0.0f);
        }

    {   // prologue: chunks 0,1 (step s0, halves 0/1)
        long o0 = (long)s0 * H2W;
        stage_t<256,128>(sb,         Arow + o0, N2);
        stage_t<256,128>(sb + TILEB, Brow + o0, N2);
        cp_commit();
        stage_t<256,128>(sb + STG,         Arow + o0 + KSTG, N2);
        stage_t<256,128>(sb + STG + TILEB, Brow + o0 + KSTG, N2);
        cp_commit();
    }

    for (int g = 0; g < nch; g++) {
        cp_wait<1>();
        __syncthreads();
        const char* buf = smem + (g % 3) * STG;
        mma32((const __nv_bfloat16*)buf,
              (const __nv_bfloat16*)(buf + TILEB), wm, wn, cf);
        __syncthreads();
        if (g + 2 < nch) {
            int gn = g + 2;
            long off = (long)(s0 + (gn >> 1)) * H2W + (gn & 1) * KSTG;
            uint32_t nb = sb + (gn % 3) * STG;
            stage_t<256,128>(nb,         Arow + off, N2);
            stage_t<256,128>(nb + TILEB, Brow + off, N2);
        }
        cp_commit();
        if (g & 1) {   // step boundary: fold (sigmoid - 0.5), reset cf
            const float coef = som[s0 + (g >> 1)];
            #pragma unroll
            for (int i = 0; i < 2; i++)
                #pragma unroll
                for (int j = 0; j < 4; j++) {
                    #pragma unroll
                    for (int e = 0; e < cf[i][j].num_elements; e++) {
                        float x = cf[i][j].x[e];
                        float x2 = x * x;
                        float q = fmaf(x2, 0.00208333333f, -0.0208333333f);
                        q = fmaf(x2, q, 0.25f);
                        float t = x * q;                 // sigmoid(x)-0.5, |x|<0.25
                        if (fabsf(x) >= 0.25f)
                            t = __fdividef(1.0f, 1.0f + __expf(-x)) - 0.5f;
                        of[i][j].x[e] = fmaf(coef, t, of[i][j].x[e]);
                        cf[i][j].x[e] = 0.0f;
                    }
                }
        }
    }

    const float inv = __fdividef(1.0f, cum[ts - 1]);
    const float bias = 0.5f * sumCoef;
    #pragma unroll
    for (int i = 0; i < 2; i++)
        #pragma unroll
        for (int j = 0; j < 4; j++) {
            #pragma unroll
            for (int e = 0; e < of[i][j].num_elements; e++)
                of[i][j].x[e] = (of[i][j].x[e] + bias) * inv;
            const int mg = by * 128 + wm * 32 + i * 16;
            const int ng = bx * 128 + wn * 64 + j * 16;
            wmma::store_matrix_sync(out + (long)mg * NROWS + ng, of[i][j],
                                    NROWS, wmma::mem_row_major);
            if (bx != by)
                wmma::store_matrix_sync(out + (long)ng * NROWS + mg, of[i][j],
                                        NROWS, wmma::mem_col_major);
        }
}

// ---------------------------------------------------------------------------
// Pre/post-processing
// ---------------------------------------------------------------------------
__global__ void cvt_bf16_kernel(const float* __restrict__ src,
                                __nv_bfloat16* __restrict__ dst, long n8) {
    long i = (long)blockIdx.x * blockDim.x + threadIdx.x;
    long stride = (long)gridDim.x * blockDim.x;
    for (; i < n8; i += stride) {
        float4 va = reinterpret_cast<const float4*>(src)[2 * i];
        float4 vb = reinterpret_cast<const float4*>(src)[2 * i + 1];
        uint4 o;
        __nv_bfloat162 h0 = __floats2bfloat162_rn(va.x, va.y);
        __nv_bfloat162 h1 = __floats2bfloat162_rn(va.z, va.w);
        __nv_bfloat162 h2 = __floats2bfloat162_rn(vb.x, vb.y);
        __nv_bfloat162 h3 = __floats2bfloat162_rn(vb.z, vb.w);
        o.x = *reinterpret_cast<uint32_t*>(&h0);
        o.y = *reinterpret_cast<uint32_t*>(&h1);
        o.z = *reinterpret_cast<uint32_t*>(&h2);
        o.w = *reinterpret_cast<uint32_t*>(&h3);
        reinterpret_cast<uint4*>(dst)[i] = o;
    }
}
// Transpose X^T (single big slab): Wt[n][k] = W[k][n] bf16
__global__ void transpose_w_kernel(const float* __restrict__ W,
                                   __nv_bfloat16* __restrict__ Wt, int K, int N) {
    for (long idx = blockIdx.x * blockDim.x + threadIdx.x; idx < (long)K * N;
         idx += (long)gridDim.x * blockDim.x) {
        long n = idx / K, k = idx % K;
        Wt[n * K + k] = __float2bfloat16(W[k * N + n]);
    }
}
// Merged W1/W2 slab transposes (y<NSTEP: W1 slab y; else W2 slab y-NSTEP)
__global__ void transpose_w2_kernel(const float* __restrict__ W1,
                                    const float* __restrict__ W2,
                                    __nv_bfloat16* __restrict__ W1t,
                                    __nv_bfloat16* __restrict__ W2t) {
    const int y = blockIdx.y;
    const float* Ws; __nv_bfloat16* Wd; int K, N;
    if (y < NSTEP) { Ws = W1 + (long)y * DIN * H1W; Wd = W1t + (long)y * DIN * H1W;
                     K = DIN; N = H1W; }
    else           { Ws = W2 + (long)(y - NSTEP) * H1W * H2W;
                     Wd = W2t + (long)(y - NSTEP) * H1W * H2W; K = H1W; N = H2W; }
    for (long idx = blockIdx.x * blockDim.x + threadIdx.x; idx < (long)K * N;
         idx += (long)gridDim.x * blockDim.x) {
        long n = idx / K, k = idx % K;
        Wd[n * K + k] = __float2bfloat16(Ws[k * N + n]);
    }
}
__global__ void mean_kernel(const float* __restrict__ H2, float* __restrict__ mean) {
    const int tx = threadIdx.x & 31;
    const int ty = threadIdx.x >> 5;
    const int col = blockIdx.x * 32 + tx;
    float s = 0.0f;
    for (int r = ty; r < NROWS; r += 8)
        s += H2[(long)r * N2 + col];
    __shared__ float red[8][32];
    red[ty][tx] = s;
    __syncthreads();
    if (ty == 0) {
        float t = 0.0f;
        #pragma unroll
        for (int i = 0; i < 8; i++) t += red[i][tx];
        mean[col] = t * (1.0f / NROWS);
    }
}
__global__ void center_kernel(const float* __restrict__ H2,
                              const float* __restrict__ mean,
                              __nv_bfloat16* __restrict__ a, long n) {
    long i = (long)blockIdx.x * blockDim.x + threadIdx.x;
    long st = (long)gridDim.x * blockDim.x;
    for (; i < n; i += st) {
        int c = (int)(i % N2);
        a[i] = __float2bfloat16(H2[i] - mean[c]);
    }
}

// ---------------------------------------------------------------------------
// Launch
// ---------------------------------------------------------------------------
extern "C" void kernel_launch(void* const* d_in, const int* in_sizes, int n_in,
                              void* d_out, int out_size) {
    const float* X   = (const float*)d_in[0];
    const float* adj = (const float*)d_in[1];
    const float* W1  = (const float*)d_in[2];
    const float* W2  = (const float*)d_in[3];
    const float* cum = (const float*)d_in[4];
    const float* som = (const float*)d_in[5];
    const int*   tsp = (const int*)d_in[6];
    const int*   Tp  = (const int*)d_in[7];
    float* out = (float*)d_out;
    (void)in_sizes; (void)n_in; (void)out_size;

    void *p_adjb, *p_xt, *p_ax, *p_w1t, *p_w2t, *p_h1, *p_t2t, *p_h2, *p_abf, *p_mean;
    cudaGetSymbolAddress(&p_adjb, g_adjb);
    cudaGetSymbolAddress(&p_xt,   g_Xt);
    cudaGetSymbolAddress(&p_ax,   g_AX);
    cudaGetSymbolAddress(&p_w1t,  g_W1t);
    cudaGetSymbolAddress(&p_w2t,  g_W2t);
    cudaGetSymbolAddress(&p_h1,   g_H1);
    cudaGetSymbolAddress(&p_t2t,  g_T2t);
    cudaGetSymbolAddress(&p_h2,   g_H2);
    cudaGetSymbolAddress(&p_abf,  g_abf);
    cudaGetSymbolAddress(&p_mean, g_mean);

    cudaFuncSetAttribute(wgemm<0>, cudaFuncAttributeMaxDynamicSharedMemorySize, GSM);
    cudaFuncSetAttribute(wgemm<1>, cudaFuncAttributeMaxDynamicSharedMemorySize, GSM);
    cudaFuncSetAttribute(wgemm<3>, cudaFuncAttributeMaxDynamicSharedMemorySize, GSM);
    cudaFuncSetAttribute(wgemm64,  cudaFuncAttributeMaxDynamicSharedMemorySize, GSM64);
    cudaFuncSetAttribute(wout,     cudaFuncAttributeMaxDynamicSharedMemorySize, GSM);

    // (1) adj -> bf16, (2) X^T, (3) merged W transposes, (4) AX ← profiled slot
    cvt_bf16_kernel<<<4096, 256>>>(adj, (__nv_bfloat16*)p_adjb, (long)NROWS * NROWS / 8);
    transpose_w_kernel<<<2048, 256>>>(X, (__nv_bfloat16*)p_xt, NROWS, DIN);
    transpose_w2_kernel<<<dim3(48, 2 * NSTEP), 256>>>(
        W1 + (size_t)DIN * H1W, W2 + (size_t)H1W * H2W,
        (__nv_bfloat16*)p_w1t, (__nv_bfloat16*)p_w2t);

    // AX = adj @ X                 [8192 x 512] bf16 (no relu) — R9 shape
    wgemm<3><<<dim3(DIN/128, NROWS/128), 128, GSM>>>(
        (const __nv_bfloat16*)p_adjb, NROWS, 0,
        (const __nv_bfloat16*)p_xt, NROWS, 0, DIN,
        (char*)p_ax, DIN, NROWS);

    // H1 = relu(AX @ W1slab)       [8192 x 1280] bf16
    wgemm<1><<<dim3(N1/128, NROWS/128), 128, GSM>>>(
        (const __nv_bfloat16*)p_ax, DIN, 0,
        (const __nv_bfloat16*)p_w1t, DIN, (long)H1W * DIN, H1W,
        (char*)p_h1, N1, DIN);

    // T2t = (H1slab @ W2slab)^T    [640 x 8192] bf16
    wgemm<0><<<dim3(N2/128, NROWS/128), 128, GSM>>>(
        (const __nv_bfloat16*)p_h1, N1, H1W,
        (const __nv_bfloat16*)p_w2t, H1W, (long)H2W * H1W, H2W,
        (char*)p_t2t, NROWS, H1W);

    // H2 = relu(adj @ T2)          [8192 x 640] f32 — 64-row tiles
    wgemm64<<<dim3(N2/128, NROWS/64), 128, GSM64>>>(
        (const __nv_bfloat16*)p_adjb, NROWS,
        (const __nv_bfloat16*)p_t2t, NROWS,
        (float*)p_h2, N2, NROWS);

    mean_kernel<<<N2 / 32, 256>>>((const float*)p_h2, (float*)p_mean);
    center_kernel<<<4096, 256>>>((const float*)p_h2, (const float*)p_mean,
                                 (__nv_bfloat16*)p_abf, (long)NROWS * N2);

    // triangular grid: 64*65/2 = 2080 CTAs
    wout<<<2080, 256, GSM>>>(
        (const __nv_bfloat16*)p_abf, som, cum, tsp, Tp, out);
}

// round 13
// speedup vs baseline: 1.0710x; 1.0530x over previous
#include <cuda_runtime.h>
#include <cuda_bf16.h>
#include <mma.h>
#include <cstdint>

using namespace nvcuda;

// ---------------------------------------------------------------------------
// Problem shape
// ---------------------------------------------------------------------------
#define NROWS 8192
#define DIN   512
#define H1W   256
#define H2W   128
#define NSTEP 5
#define N1 (NSTEP*H1W)   // 1280
#define N2 (NSTEP*H2W)   // 640

#define KSTG  64
#define SLD   72                 // smem row stride in bf16 (144B)
#define TILEB (128*SLD*2)        // 18432 per 128x64 tile
#define STG   (2*TILEB)          // 36864 per stage (A+B)
#define GSM   (3*STG)            // 110592 — 2 CTAs/SM
#define CLD   129
// H2 variant: 64-row A tile, 2-stage pipeline, 4 CTAs/SM
#define ATIL64 (64*SLD*2)        // 9216
#define STG64  (ATIL64+TILEB)    // 27648
#define GSM64  (2*STG64)         // 55296 — 4 CTAs/SM

// ---------------------------------------------------------------------------
// Scratch (device globals)
// ---------------------------------------------------------------------------
__device__ __nv_bfloat16 g_adjb[(size_t)NROWS*NROWS];
__device__ __nv_bfloat16 g_Xt  [(size_t)DIN*NROWS];      // X^T bf16
__device__ __nv_bfloat16 g_AX  [(size_t)NROWS*DIN];      // adj@X bf16
__device__ __nv_bfloat16 g_W1t [(size_t)NSTEP*H1W*DIN];  // [s][n][k]
__device__ __nv_bfloat16 g_W2t [(size_t)NSTEP*H2W*H1W];  // [s][n][k]
__device__ __nv_bfloat16 g_H1  [(size_t)NROWS*N1];       // relu(AX@W1) bf16
__device__ __nv_bfloat16 g_T2t [(size_t)N2*NROWS];       // (H1@W2)^T bf16
__device__ float         g_H2  [(size_t)NROWS*N2];       // relu(adj@T2) f32
__device__ __nv_bfloat16 g_abf [(size_t)NROWS*N2];       // centered a bf16
__device__ float         g_mean[N2];

// ---------------------------------------------------------------------------
// Helpers
// ---------------------------------------------------------------------------
static __device__ __forceinline__ void cp16(uint32_t sdst, const void* g) {
    asm volatile("cp.async.cg.shared.global [%0], [%1], 16;"
                 :: "r"(sdst), "l"(g) : "memory");
}
static __device__ __forceinline__ void cp_commit() {
    asm volatile("cp.async.commit_group;" ::: "memory");
}
template <int N>
static __device__ __forceinline__ void cp_wait() {
    asm volatile("cp.async.wait_group %0;" :: "n"(N) : "memory");
}
static __device__ __forceinline__ uint32_t smem_u32(const void* p) {
    uint32_t a;
    asm("{ .reg .u64 t; cvta.to.shared.u64 t, %1; cvt.u32.u64 %0, t; }"
        : "=r"(a) : "l"(p));
    return a;
}
// Poly for |x|<0.25 (abs err < 2e-8), per-element exact fallback otherwise.
static __device__ __forceinline__ float fast_sigmoid(float x) {
    float ax = fabsf(x);
    float x2 = x * x;
    float p = 0.5f + x * (0.25f + x2 * (-0.0208333333f + x2 * 0.00208333333f));
    if (ax >= 0.25f) p = __fdividef(1.0f, 1.0f + __expf(-x));
    return p;
}

// Stage an NRxKSTG bf16 tile (row stride SLD); NT = threads in CTA.
template <int NT, int NR>
static __device__ __forceinline__ void stage_t(uint32_t sdst,
                                               const __nv_bfloat16* __restrict__ src,
                                               long ld) {
    const int t = threadIdx.x;
    #pragma unroll
    for (int i = 0; i < NR * 8 / NT; i++) {
        int c = t + i * NT;
        int row = c >> 3, col = c & 7;
        cp16(sdst + row * (SLD * 2) + col * 16, src + (long)row * ld + col * 8);
    }
}

// 64x64 warp tile over one 64-K chunk
template <typename FragC>
static __device__ __forceinline__ void mma64(const __nv_bfloat16* As,
                                             const __nv_bfloat16* Bs,
                                             int wm, int wn, FragC (&cf)[4][4]) {
    #pragma unroll
    for (int kk = 0; kk < KSTG; kk += 16) {
        wmma::fragment<wmma::matrix_a, 16, 16, 16, __nv_bfloat16, wmma::row_major> af[4];
        wmma::fragment<wmma::matrix_b, 16, 16, 16, __nv_bfloat16, wmma::col_major> bf[4];
        #pragma unroll
        for (int i = 0; i < 4; i++)
            wmma::load_matrix_sync(af[i], As + (wm * 64 + i * 16) * SLD + kk, SLD);
        #pragma unroll
        for (int j = 0; j < 4; j++)
            wmma::load_matrix_sync(bf[j], Bs + (wn * 64 + j * 16) * SLD + kk, SLD);
        #pragma unroll
        for (int i = 0; i < 4; i++)
            #pragma unroll
            for (int j = 0; j < 4; j++)
                wmma::mma_sync(cf[i][j], af[i], bf[j], cf[i][j]);
    }
}

// 32x64 warp tile over one 64-K chunk
template <typename FragC>
static __device__ __forceinline__ void mma32(const __nv_bfloat16* As,
                                             const __nv_bfloat16* Bs,
                                             int wm, int wn, FragC (&cf)[2][4]) {
    #pragma unroll
    for (int kk = 0; kk < KSTG; kk += 16) {
        wmma::fragment<wmma::matrix_a, 16, 16, 16, __nv_bfloat16, wmma::row_major> af[2];
        wmma::fragment<wmma::matrix_b, 16, 16, 16, __nv_bfloat16, wmma::col_major> bf[4];
        #pragma unroll
        for (int i = 0; i < 2; i++)
            wmma::load_matrix_sync(af[i], As + (wm * 32 + i * 16) * SLD + kk, SLD);
        #pragma unroll
        for (int j = 0; j < 4; j++)
            wmma::load_matrix_sync(bf[j], Bs + (wn * 64 + j * 16) * SLD + kk, SLD);
        #pragma unroll
        for (int i = 0; i < 2; i++)
            #pragma unroll
            for (int j = 0; j < 4; j++)
                wmma::mma_sync(cf[i][j], af[i], bf[j], cf[i][j]);
    }
}

// ---------------------------------------------------------------------------
// 3-stage pipelined GEMM (two-sync schedule): C = op(A[M,K] @ B[N,K]^T).
// CTA 128x128, 4 warps, 64x64 warp tiles.
// EPI: 0 = bf16 transposed, 1 = bf16 row + relu, 3 = bf16 row (no relu)
// ---------------------------------------------------------------------------
template <int EPI>
__global__ void __launch_bounds__(128)
wgemm(const __nv_bfloat16* __restrict__ A, long lda, long aSlabCol,
      const __nv_bfloat16* __restrict__ B, long ldb, long bSlabStride, int outSlabN,
      char* __restrict__ Cv, long ldc, int K) {
    extern __shared__ char smem[];
    const uint32_t sb = smem_u32(smem);
    const int tid = threadIdx.x, warp = tid >> 5;
    const int wm = warp >> 1, wn = warp & 1;    // 2x2 warps, 64x64 each
    const int bx = blockIdx.x, by = blockIdx.y;

    const int slab = (bx * 128) / outSlabN;
    const __nv_bfloat16* Ab = A + (long)(by * 128) * lda + (long)slab * aSlabCol;
    const __nv_bfloat16* Bb = B + (long)slab * bSlabStride
                                + (long)((bx * 128) % outSlabN) * ldb;

    wmma::fragment<wmma::accumulator, 16, 16, 16, float> cf[4][4];
    #pragma unroll
    for (int i = 0; i < 4; i++)
        #pragma unroll
        for (int j = 0; j < 4; j++) wmma::fill_fragment(cf[i][j], 0.0f);

    const int KT = K >> 6;
    // prologue: stages 0, 1
    stage_t<128,128>(sb,         Ab,        lda);
    stage_t<128,128>(sb + TILEB, Bb,        ldb);
    cp_commit();
    stage_t<128,128>(sb + STG,         Ab + KSTG, lda);
    stage_t<128,128>(sb + STG + TILEB, Bb + KSTG, ldb);
    cp_commit();

    for (int t = 0; t < KT; t++) {
        cp_wait<1>();
        __syncthreads();
        const char* buf = smem + (t % 3) * STG;
        mma64((const __nv_bfloat16*)buf,
              (const __nv_bfloat16*)(buf + TILEB), wm, wn, cf);
        __syncthreads();
        if (t + 2 < KT) {
            const uint32_t nb = sb + ((t + 2) % 3) * STG;
            stage_t<128,128>(nb,         Ab + (long)(t + 2) * KSTG, lda);
            stage_t<128,128>(nb + TILEB, Bb + (long)(t + 2) * KSTG, ldb);
        }
        cp_commit();   // uniform cadence
    }

    // bf16 outputs via smem Cs[128][129] f32 (reuses stage buffers)
    float* Cs = (float*)smem;
    #pragma unroll
    for (int i = 0; i < 4; i++)
        #pragma unroll
        for (int j = 0; j < 4; j++)
            wmma::store_matrix_sync(Cs + (wm * 64 + i * 16) * CLD + wn * 64 + j * 16,
                                    cf[i][j], CLD, wmma::mem_row_major);
    __syncthreads();

    if (EPI == 0) {
        // transposed bf16: thread owns column n = tid, all 128 m values
        const int n = tid;
        __nv_bfloat16* dst = (__nv_bfloat16*)Cv + (long)(bx * 128 + n) * ldc
                                                + (long)by * 128;
        #pragma unroll
        for (int pass = 0; pass < 2; pass++) {
            uint32_t pk[32];
            #pragma unroll
            for (int k = 0; k < 32; k++) {
                int m = pass * 64 + 2 * k;
                __nv_bfloat162 h = __floats2bfloat162_rn(Cs[m * CLD + n],
                                                         Cs[(m + 1) * CLD + n]);
                pk[k] = *reinterpret_cast<uint32_t*>(&h);
            }
            #pragma unroll
            for (int i = 0; i < 8; i++)
                reinterpret_cast<uint4*>(dst + pass * 64)[i] =
                    *reinterpret_cast<uint4*>(pk + 4 * i);
        }
    } else {
        // row-major bf16: thread owns row m = tid (relu iff EPI==1)
        const int m = tid;
        __nv_bfloat16* dst = (__nv_bfloat16*)Cv + (long)(by * 128 + m) * ldc
                                                + (long)bx * 128;
        #pragma unroll
        for (int pass = 0; pass < 2; pass++) {
            uint32_t pk[32];
            #pragma unroll
            for (int k = 0; k < 32; k++) {
                int c = pass * 64 + 2 * k;
                float a = Cs[m * CLD + c];
                float b = Cs[m * CLD + c + 1];
                if (EPI == 1) { a = fmaxf(a, 0.0f); b = fmaxf(b, 0.0f); }
                __nv_bfloat162 h = __floats2bfloat162_rn(a, b);
                pk[k] = *reinterpret_cast<uint32_t*>(&h);
            }
            #pragma unroll
            for (int i = 0; i < 8; i++)
                reinterpret_cast<uint4*>(dst + pass * 64)[i] =
                    *reinterpret_cast<uint4*>(pk + 4 * i);
        }
    }
}

// ---------------------------------------------------------------------------
// H2 variant: CTA 64x128, 4 warps of 32x64, TWO-stage pipeline, 4 CTAs/SM
// (regs capped at 128 via launch_bounds minBlocks=4). f32 row + relu output.
// ---------------------------------------------------------------------------
__global__ void __launch_bounds__(128, 4)
wgemm64(const __nv_bfloat16* __restrict__ A, long lda,
        const __nv_bfloat16* __restrict__ B, long ldb,
        float* __restrict__ C, long ldc, int K) {
    extern __shared__ char smem[];
    const uint32_t sb = smem_u32(smem);
    const int tid = threadIdx.x, warp = tid >> 5;
    const int wm = warp >> 1, wn = warp & 1;    // 2x2 warps, 32x64 each
    const int bx = blockIdx.x, by = blockIdx.y;

    const __nv_bfloat16* Ab = A + (long)(by * 64) * lda;
    const __nv_bfloat16* Bb = B + (long)(bx * 128) * ldb;

    wmma::fragment<wmma::accumulator, 16, 16, 16, float> cf[2][4];
    #pragma unroll
    for (int i = 0; i < 2; i++)
        #pragma unroll
        for (int j = 0; j < 4; j++) wmma::fill_fragment(cf[i][j], 0.0f);

    const int KT = K >> 6;
    stage_t<128,64> (sb,          Ab,        lda);
    stage_t<128,128>(sb + ATIL64, Bb,        ldb);
    cp_commit();
    stage_t<128,64> (sb + STG64,          Ab + KSTG, lda);
    stage_t<128,128>(sb + STG64 + ATIL64, Bb + KSTG, ldb);
    cp_commit();

    for (int t = 0; t < KT; t++) {
        cp_wait<1>();
        __syncthreads();
        const char* buf = smem + (t & 1) * STG64;
        mma32((const __nv_bfloat16*)buf,
              (const __nv_bfloat16*)(buf + ATIL64), wm, wn, cf);
        __syncthreads();
        if (t + 2 < KT) {
            const uint32_t nb = sb + (t & 1) * STG64;   // (t+2)&1 == t&1
            stage_t<128,64> (nb,          Ab + (long)(t + 2) * KSTG, lda);
            stage_t<128,128>(nb + ATIL64, Bb + (long)(t + 2) * KSTG, ldb);
        }
        cp_commit();
    }

    #pragma unroll
    for (int i = 0; i < 2; i++)
        #pragma unroll
        for (int j = 0; j < 4; j++) {
            #pragma unroll
            for (int e = 0; e < cf[i][j].num_elements; e++)
                cf[i][j].x[e] = fmaxf(cf[i][j].x[e], 0.0f);
            float* Cp = C + (long)(by * 64 + wm * 32 + i * 16) * ldc
                          + (long)bx * 128 + wn * 64 + j * 16;
            wmma::store_matrix_sync(Cp, cf[i][j], ldc, wmma::mem_row_major);
        }
}

// ---------------------------------------------------------------------------
// Output kernel (R9 version, unchanged): symmetric (bx>=by), two-sync
// 3-buffer pipeline, 8 warps of 32x64, sigmoid fold, mirrored stores.
// ---------------------------------------------------------------------------
__global__ void __launch_bounds__(256)
wout(const __nv_bfloat16* __restrict__ a,
     const float* __restrict__ som, const float* __restrict__ cum,
     const int* __restrict__ tsp, const int* __restrict__ Tp,
     float* __restrict__ out) {
    const int bx = blockIdx.x, by = blockIdx.y;
    if (bx < by) return;
    extern __shared__ char smem[];
    const uint32_t sb = smem_u32(smem);
    const int tid = threadIdx.x, warp = tid >> 5;
    const int wm = warp >> 1, wn = warp & 1;
    const int ts = *tsp, T = *Tp;
    const int s0 = ts - 1, nch = 2 * (T - ts + 1);

    const __nv_bfloat16* Arow = a + (long)(by * 128) * N2;
    const __nv_bfloat16* Brow = a + (long)(bx * 128) * N2;

    wmma::fragment<wmma::accumulator, 16, 16, 16, float> of[2][4], cf[2][4];
    #pragma unroll
    for (int i = 0; i < 2; i++)
        #pragma unroll
        for (int j = 0; j < 4; j++) {
            wmma::fill_fragment(of[i][j], 0.0f);
            wmma::fill_fragment(cf[i][j], 0.0f);
        }

    {   // prologue: chunks 0,1 (step s0, halves 0/1)
        long o0 = (long)s0 * H2W;
        stage_t<256,128>(sb,         Arow + o0, N2);
        stage_t<256,128>(sb + TILEB, Brow + o0, N2);
        cp_commit();
        stage_t<256,128>(sb + STG,         Arow + o0 + KSTG, N2);
        stage_t<256,128>(sb + STG + TILEB, Brow + o0 + KSTG, N2);
        cp_commit();
    }

    for (int g = 0; g < nch; g++) {
        cp_wait<1>();
        __syncthreads();
        const char* buf = smem + (g % 3) * STG;
        mma32((const __nv_bfloat16*)buf,
              (const __nv_bfloat16*)(buf + TILEB), wm, wn, cf);
        __syncthreads();
        if (g + 2 < nch) {
            int gn = g + 2;
            long off = (long)(s0 + (gn >> 1)) * H2W + (gn & 1) * KSTG;
            uint32_t nb = sb + (gn % 3) * STG;
            stage_t<256,128>(nb,         Arow + off, N2);
            stage_t<256,128>(nb + TILEB, Brow + off, N2);
        }
        cp_commit();
        if (g & 1) {   // step boundary: fold sigmoid, reset cf
            const float coef = som[s0 + (g >> 1)];
            #pragma unroll
            for (int i = 0; i < 2; i++)
                #pragma unroll
                for (int j = 0; j < 4; j++) {
                    #pragma unroll
                    for (int e = 0; e < cf[i][j].num_elements; e++) {
                        of[i][j].x[e] += coef * fast_sigmoid(cf[i][j].x[e]);
                        cf[i][j].x[e] = 0.0f;
                    }
                }
        }
    }

    const float inv = __fdividef(1.0f, cum[ts - 1]);
    #pragma unroll
    for (int i = 0; i < 2; i++)
        #pragma unroll
        for (int j = 0; j < 4; j++) {
            #pragma unroll
            for (int e = 0; e < of[i][j].num_elements; e++)
                of[i][j].x[e] *= inv;
            const int mg = by * 128 + wm * 32 + i * 16;
            const int ng = bx * 128 + wn * 64 + j * 16;
            wmma::store_matrix_sync(out + (long)mg * NROWS + ng, of[i][j],
                                    NROWS, wmma::mem_row_major);
            if (bx != by)
                wmma::store_matrix_sync(out + (long)ng * NROWS + mg, of[i][j],
                                        NROWS, wmma::mem_col_major);
        }
}

// ---------------------------------------------------------------------------
// Pre/post-processing
// ---------------------------------------------------------------------------
__global__ void cvt_bf16_kernel(const float* __restrict__ src,
                                __nv_bfloat16* __restrict__ dst, long n8) {
    long i = (long)blockIdx.x * blockDim.x + threadIdx.x;
    long stride = (long)gridDim.x * blockDim.x;
    for (; i < n8; i += stride) {
        float4 va = reinterpret_cast<const float4*>(src)[2 * i];
        float4 vb = reinterpret_cast<const float4*>(src)[2 * i + 1];
        uint4 o;
        __nv_bfloat162 h0 = __floats2bfloat162_rn(va.x, va.y);
        __nv_bfloat162 h1 = __floats2bfloat162_rn(va.z, va.w);
        __nv_bfloat162 h2 = __floats2bfloat162_rn(vb.x, vb.y);
        __nv_bfloat162 h3 = __floats2bfloat162_rn(vb.z, vb.w);
        o.x = *reinterpret_cast<uint32_t*>(&h0);
        o.y = *reinterpret_cast<uint32_t*>(&h1);
        o.z = *reinterpret_cast<uint32_t*>(&h2);
        o.w = *reinterpret_cast<uint32_t*>(&h3);
        reinterpret_cast<uint4*>(dst)[i] = o;
    }
}
// Transpose X^T (single big slab): Wt[n][k] = W[k][n] bf16
__global__ void transpose_w_kernel(const float* __restrict__ W,
                                   __nv_bfloat16* __restrict__ Wt, int K, int N) {
    for (long idx = blockIdx.x * blockDim.x + threadIdx.x; idx < (long)K * N;
         idx += (long)gridDim.x * blockDim.x) {
        long n = idx / K, k = idx % K;
        Wt[n * K + k] = __float2bfloat16(W[k * N + n]);
    }
}
// Merged W1/W2 slab transposes (y<NSTEP: W1 slab y; else W2 slab y-NSTEP)
__global__ void transpose_w2_kernel(const float* __restrict__ W1,
                                    const float* __restrict__ W2,
                                    __nv_bfloat16* __restrict__ W1t,
                                    __nv_bfloat16* __restrict__ W2t) {
    const int y = blockIdx.y;
    const float* Ws; __nv_bfloat16* Wd; int K, N;
    if (y < NSTEP) { Ws = W1 + (long)y * DIN * H1W; Wd = W1t + (long)y * DIN * H1W;
                     K = DIN; N = H1W; }
    else           { Ws = W2 + (long)(y - NSTEP) * H1W * H2W;
                     Wd = W2t + (long)(y - NSTEP) * H1W * H2W; K = H1W; N = H2W; }
    for (long idx = blockIdx.x * blockDim.x + threadIdx.x; idx < (long)K * N;
         idx += (long)gridDim.x * blockDim.x) {
        long n = idx / K, k = idx % K;
        Wd[n * K + k] = __float2bfloat16(Ws[k * N + n]);
    }
}
__global__ void mean_kernel(const float* __restrict__ H2, float* __restrict__ mean) {
    const int tx = threadIdx.x & 31;
    const int ty = threadIdx.x >> 5;
    const int col = blockIdx.x * 32 + tx;
    float s = 0.0f;
    for (int r = ty; r < NROWS; r += 8)
        s += H2[(long)r * N2 + col];
    __shared__ float red[8][32];
    red[ty][tx] = s;
    __syncthreads();
    if (ty == 0) {
        float t = 0.0f;
        #pragma unroll
        for (int i = 0; i < 8; i++) t += red[i][tx];
        mean[col] = t * (1.0f / NROWS);
    }
}
__global__ void center_kernel(const float* __restrict__ H2,
                              const float* __restrict__ mean,
                              __nv_bfloat16* __restrict__ a, long n) {
    long i = (long)blockIdx.x * blockDim.x + threadIdx.x;
    long st = (long)gridDim.x * blockDim.x;
    for (; i < n; i += st) {
        int c = (int)(i % N2);
        a[i] = __float2bfloat16(H2[i] - mean[c]);
    }
}

// ---------------------------------------------------------------------------
// Launch
// ---------------------------------------------------------------------------
extern "C" void kernel_launch(void* const* d_in, const int* in_sizes, int n_in,
                              void* d_out, int out_size) {
    const float* X   = (const float*)d_in[0];
    const float* adj = (const float*)d_in[1];
    const float* W1  = (const float*)d_in[2];
    const float* W2  = (const float*)d_in[3];
    const float* cum = (const float*)d_in[4];
    const float* som = (const float*)d_in[5];
    const int*   tsp = (const int*)d_in[6];
    const int*   Tp  = (const int*)d_in[7];
    float* out = (float*)d_out;
    (void)in_sizes; (void)n_in; (void)out_size;

    void *p_adjb, *p_xt, *p_ax, *p_w1t, *p_w2t, *p_h1, *p_t2t, *p_h2, *p_abf, *p_mean;
    cudaGetSymbolAddress(&p_adjb, g_adjb);
    cudaGetSymbolAddress(&p_xt,   g_Xt);
    cudaGetSymbolAddress(&p_ax,   g_AX);
    cudaGetSymbolAddress(&p_w1t,  g_W1t);
    cudaGetSymbolAddress(&p_w2t,  g_W2t);
    cudaGetSymbolAddress(&p_h1,   g_H1);
    cudaGetSymbolAddress(&p_t2t,  g_T2t);
    cudaGetSymbolAddress(&p_h2,   g_H2);
    cudaGetSymbolAddress(&p_abf,  g_abf);
    cudaGetSymbolAddress(&p_mean, g_mean);

    cudaFuncSetAttribute(wgemm<0>, cudaFuncAttributeMaxDynamicSharedMemorySize, GSM);
    cudaFuncSetAttribute(wgemm<1>, cudaFuncAttributeMaxDynamicSharedMemorySize, GSM);
    cudaFuncSetAttribute(wgemm<3>, cudaFuncAttributeMaxDynamicSharedMemorySize, GSM);
    cudaFuncSetAttribute(wgemm64,  cudaFuncAttributeMaxDynamicSharedMemorySize, GSM64);
    cudaFuncSetAttribute(wout,     cudaFuncAttributeMaxDynamicSharedMemorySize, GSM);

    // (1) adj -> bf16, (2) X^T, (3) merged W transposes, (4) AX ← profiled slot
    cvt_bf16_kernel<<<4096, 256>>>(adj, (__nv_bfloat16*)p_adjb, (long)NROWS * NROWS / 8);
    transpose_w_kernel<<<2048, 256>>>(X, (__nv_bfloat16*)p_xt, NROWS, DIN);
    transpose_w2_kernel<<<dim3(48, 2 * NSTEP), 256>>>(
        W1 + (size_t)DIN * H1W, W2 + (size_t)H1W * H2W,
        (__nv_bfloat16*)p_w1t, (__nv_bfloat16*)p_w2t);

    // AX = adj @ X                 [8192 x 512] bf16 (no relu)
    wgemm<3><<<dim3(DIN/128, NROWS/128), 128, GSM>>>(
        (const __nv_bfloat16*)p_adjb, NROWS, 0,
        (const __nv_bfloat16*)p_xt, NROWS, 0, DIN,
        (char*)p_ax, DIN, NROWS);

    // H1 = relu(AX @ W1slab)       [8192 x 1280] bf16
    wgemm<1><<<dim3(N1/128, NROWS/128), 128, GSM>>>(
        (const __nv_bfloat16*)p_ax, DIN, 0,
        (const __nv_bfloat16*)p_w1t, DIN, (long)H1W * DIN, H1W,
        (char*)p_h1, N1, DIN);

    // T2t = (H1slab @ W2slab)^T    [640 x 8192] bf16
    wgemm<0><<<dim3(N2/128, NROWS/128), 128, GSM>>>(
        (const __nv_bfloat16*)p_h1, N1, H1W,
        (const __nv_bfloat16*)p_w2t, H1W, (long)H2W * H1W, H2W,
        (char*)p_t2t, NROWS, H1W);

    // H2 = relu(adj @ T2)  [8192 x 640] f32 — 64-row tiles, 2-stage, 4 CTAs/SM
    wgemm64<<<dim3(N2/128, NROWS/64), 128, GSM64>>>(
        (const __nv_bfloat16*)p_adjb, NROWS,
        (const __nv_bfloat16*)p_t2t, NROWS,
        (float*)p_h2, N2, NROWS);

    mean_kernel<<<N2 / 32, 256>>>((const float*)p_h2, (float*)p_mean);
    center_kernel<<<4096, 256>>>((const float*)p_h2, (const float*)p_mean,
                                 (__nv_bfloat16*)p_abf, (long)NROWS * N2);

    wout<<<dim3(NROWS/128, NROWS/128), 256, GSM>>>(
        (const __nv_bfloat16*)p_abf, som, cum, tsp, Tp, out);
}

// round 14
// speedup vs baseline: 1.0926x; 1.0202x over previous
#include <cuda_runtime.h>
#include <cuda_bf16.h>
#include <mma.h>
#include <cstdint>

using namespace nvcuda;

// ---------------------------------------------------------------------------
// Problem shape
// ---------------------------------------------------------------------------
#define NROWS 8192
#define DIN   512
#define H1W   256
#define H2W   128
#define NSTEP 5
#define N1 (NSTEP*H1W)   // 1280
#define N2 (NSTEP*H2W)   // 640

#define KSTG  64
#define SLD   72                 // smem row stride in bf16 (144B)
#define TILEB (128*SLD*2)        // 18432 per 128x64 tile
#define STG   (2*TILEB)          // 36864 per stage (A+B)
#define GSM   (3*STG)            // 110592
#define CLD   129
// H2 variant: 64-row A tile, 2-stage pipeline, 4 CTAs/SM
#define ATIL64 (64*SLD*2)        // 9216
#define STG64  (ATIL64+TILEB)    // 27648
#define GSM64  (2*STG64)         // 55296 — 4 CTAs/SM

// ---------------------------------------------------------------------------
// Scratch (device globals)
// ---------------------------------------------------------------------------
__device__ __nv_bfloat16 g_adjb[(size_t)NROWS*NROWS];
__device__ __nv_bfloat16 g_Xt  [(size_t)DIN*NROWS];      // X^T bf16
__device__ __nv_bfloat16 g_AX  [(size_t)NROWS*DIN];      // adj@X bf16
__device__ __nv_bfloat16 g_W1t [(size_t)NSTEP*H1W*DIN];  // [s][n][k]
__device__ __nv_bfloat16 g_W2t [(size_t)NSTEP*H2W*H1W];  // [s][n][k]
__device__ __nv_bfloat16 g_H1  [(size_t)NROWS*N1];       // relu(AX@W1) bf16
__device__ __nv_bfloat16 g_T2t [(size_t)N2*NROWS];       // (H1@W2)^T bf16
__device__ float         g_H2  [(size_t)NROWS*N2];       // relu(adj@T2) f32
__device__ __nv_bfloat16 g_abf [(size_t)NROWS*N2];       // centered a bf16
__device__ float         g_mean[N2];

// ---------------------------------------------------------------------------
// Helpers
// ---------------------------------------------------------------------------
static __device__ __forceinline__ void cp16(uint32_t sdst, const void* g) {
    asm volatile("cp.async.cg.shared.global [%0], [%1], 16;"
                 :: "r"(sdst), "l"(g) : "memory");
}
static __device__ __forceinline__ void cp_commit() {
    asm volatile("cp.async.commit_group;" ::: "memory");
}
template <int N>
static __device__ __forceinline__ void cp_wait() {
    asm volatile("cp.async.wait_group %0;" :: "n"(N) : "memory");
}
static __device__ __forceinline__ uint32_t smem_u32(const void* p) {
    uint32_t a;
    asm("{ .reg .u64 t; cvta.to.shared.u64 t, %1; cvt.u32.u64 %0, t; }"
        : "=r"(a) : "l"(p));
    return a;
}
// Poly for |x|<0.25 (abs err < 2e-8), per-element exact fallback otherwise.
static __device__ __forceinline__ float fast_sigmoid(float x) {
    float ax = fabsf(x);
    float x2 = x * x;
    float p = 0.5f + x * (0.25f + x2 * (-0.0208333333f + x2 * 0.00208333333f));
    if (ax >= 0.25f) p = __fdividef(1.0f, 1.0f + __expf(-x));
    return p;
}

// Stage an NRxKSTG bf16 tile (row stride SLD); NT = threads in CTA.
template <int NT, int NR>
static __device__ __forceinline__ void stage_t(uint32_t sdst,
                                               const __nv_bfloat16* __restrict__ src,
                                               long ld) {
    const int t = threadIdx.x;
    #pragma unroll
    for (int i = 0; i < NR * 8 / NT; i++) {
        int c = t + i * NT;
        int row = c >> 3, col = c & 7;
        cp16(sdst + row * (SLD * 2) + col * 16, src + (long)row * ld + col * 8);
    }
}

// 64x64 warp tile over one 64-K chunk
template <typename FragC>
static __device__ __forceinline__ void mma64(const __nv_bfloat16* As,
                                             const __nv_bfloat16* Bs,
                                             int wm, int wn, FragC (&cf)[4][4]) {
    #pragma unroll
    for (int kk = 0; kk < KSTG; kk += 16) {
        wmma::fragment<wmma::matrix_a, 16, 16, 16, __nv_bfloat16, wmma::row_major> af[4];
        wmma::fragment<wmma::matrix_b, 16, 16, 16, __nv_bfloat16, wmma::col_major> bf[4];
        #pragma unroll
        for (int i = 0; i < 4; i++)
            wmma::load_matrix_sync(af[i], As + (wm * 64 + i * 16) * SLD + kk, SLD);
        #pragma unroll
        for (int j = 0; j < 4; j++)
            wmma::load_matrix_sync(bf[j], Bs + (wn * 64 + j * 16) * SLD + kk, SLD);
        #pragma unroll
        for (int i = 0; i < 4; i++)
            #pragma unroll
            for (int j = 0; j < 4; j++)
                wmma::mma_sync(cf[i][j], af[i], bf[j], cf[i][j]);
    }
}

// 32x64 warp tile over one 64-K chunk
template <typename FragC>
static __device__ __forceinline__ void mma32(const __nv_bfloat16* As,
                                             const __nv_bfloat16* Bs,
                                             int wm, int wn, FragC (&cf)[2][4]) {
    #pragma unroll
    for (int kk = 0; kk < KSTG; kk += 16) {
        wmma::fragment<wmma::matrix_a, 16, 16, 16, __nv_bfloat16, wmma::row_major> af[2];
        wmma::fragment<wmma::matrix_b, 16, 16, 16, __nv_bfloat16, wmma::col_major> bf[4];
        #pragma unroll
        for (int i = 0; i < 2; i++)
            wmma::load_matrix_sync(af[i], As + (wm * 32 + i * 16) * SLD + kk, SLD);
        #pragma unroll
        for (int j = 0; j < 4; j++)
            wmma::load_matrix_sync(bf[j], Bs + (wn * 64 + j * 16) * SLD + kk, SLD);
        #pragma unroll
        for (int i = 0; i < 2; i++)
            #pragma unroll
            for (int j = 0; j < 4; j++)
                wmma::mma_sync(cf[i][j], af[i], bf[j], cf[i][j]);
    }
}

// ---------------------------------------------------------------------------
// 3-stage pipelined GEMM (two-sync schedule): C = op(A[M,K] @ B[N,K]^T).
// CTA 128x128, 4 warps, 64x64 warp tiles.
// EPI: 0 = bf16 transposed, 1 = bf16 row + relu, 3 = bf16 row (no relu)
// ---------------------------------------------------------------------------
template <int EPI>
__global__ void __launch_bounds__(128)
wgemm(const __nv_bfloat16* __restrict__ A, long lda, long aSlabCol,
      const __nv_bfloat16* __restrict__ B, long ldb, long bSlabStride, int outSlabN,
      char* __restrict__ Cv, long ldc, int K) {
    extern __shared__ char smem[];
    const uint32_t sb = smem_u32(smem);
    const int tid = threadIdx.x, warp = tid >> 5;
    const int wm = warp >> 1, wn = warp & 1;    // 2x2 warps, 64x64 each
    const int bx = blockIdx.x, by = blockIdx.y;

    const int slab = (bx * 128) / outSlabN;
    const __nv_bfloat16* Ab = A + (long)(by * 128) * lda + (long)slab * aSlabCol;
    const __nv_bfloat16* Bb = B + (long)slab * bSlabStride
                                + (long)((bx * 128) % outSlabN) * ldb;

    wmma::fragment<wmma::accumulator, 16, 16, 16, float> cf[4][4];
    #pragma unroll
    for (int i = 0; i < 4; i++)
        #pragma unroll
        for (int j = 0; j < 4; j++) wmma::fill_fragment(cf[i][j], 0.0f);

    const int KT = K >> 6;
    // prologue: stages 0, 1
    stage_t<128,128>(sb,         Ab,        lda);
    stage_t<128,128>(sb + TILEB, Bb,        ldb);
    cp_commit();
    stage_t<128,128>(sb + STG,         Ab + KSTG, lda);
    stage_t<128,128>(sb + STG + TILEB, Bb + KSTG, ldb);
    cp_commit();

    for (int t = 0; t < KT; t++) {
        cp_wait<1>();
        __syncthreads();
        const char* buf = smem + (t % 3) * STG;
        mma64((const __nv_bfloat16*)buf,
              (const __nv_bfloat16*)(buf + TILEB), wm, wn, cf);
        __syncthreads();
        if (t + 2 < KT) {
            const uint32_t nb = sb + ((t + 2) % 3) * STG;
            stage_t<128,128>(nb,         Ab + (long)(t + 2) * KSTG, lda);
            stage_t<128,128>(nb + TILEB, Bb + (long)(t + 2) * KSTG, ldb);
        }
        cp_commit();   // uniform cadence
    }

    // bf16 outputs via smem Cs[128][129] f32 (reuses stage buffers)
    float* Cs = (float*)smem;
    #pragma unroll
    for (int i = 0; i < 4; i++)
        #pragma unroll
        for (int j = 0; j < 4; j++)
            wmma::store_matrix_sync(Cs + (wm * 64 + i * 16) * CLD + wn * 64 + j * 16,
                                    cf[i][j], CLD, wmma::mem_row_major);
    __syncthreads();

    if (EPI == 0) {
        // transposed bf16: thread owns column n = tid, all 128 m values
        const int n = tid;
        __nv_bfloat16* dst = (__nv_bfloat16*)Cv + (long)(bx * 128 + n) * ldc
                                                + (long)by * 128;
        #pragma unroll
        for (int pass = 0; pass < 2; pass++) {
            uint32_t pk[32];
            #pragma unroll
            for (int k = 0; k < 32; k++) {
                int m = pass * 64 + 2 * k;
                __nv_bfloat162 h = __floats2bfloat162_rn(Cs[m * CLD + n],
                                                         Cs[(m + 1) * CLD + n]);
                pk[k] = *reinterpret_cast<uint32_t*>(&h);
            }
            #pragma unroll
            for (int i = 0; i < 8; i++)
                reinterpret_cast<uint4*>(dst + pass * 64)[i] =
                    *reinterpret_cast<uint4*>(pk + 4 * i);
        }
    } else {
        // row-major bf16: thread owns row m = tid (relu iff EPI==1)
        const int m = tid;
        __nv_bfloat16* dst = (__nv_bfloat16*)Cv + (long)(by * 128 + m) * ldc
                                                + (long)bx * 128;
        #pragma unroll
        for (int pass = 0; pass < 2; pass++) {
            uint32_t pk[32];
            #pragma unroll
            for (int k = 0; k < 32; k++) {
                int c = pass * 64 + 2 * k;
                float a = Cs[m * CLD + c];
                float b = Cs[m * CLD + c + 1];
                if (EPI == 1) { a = fmaxf(a, 0.0f); b = fmaxf(b, 0.0f); }
                __nv_bfloat162 h = __floats2bfloat162_rn(a, b);
                pk[k] = *reinterpret_cast<uint32_t*>(&h);
            }
            #pragma unroll
            for (int i = 0; i < 8; i++)
                reinterpret_cast<uint4*>(dst + pass * 64)[i] =
                    *reinterpret_cast<uint4*>(pk + 4 * i);
        }
    }
}

// ---------------------------------------------------------------------------
// H2 variant: CTA 64x128, 4 warps of 32x64, TWO-stage pipeline, 4 CTAs/SM.
// f32 row-major + relu output. (R13 WIN configuration.)
// ---------------------------------------------------------------------------
__global__ void __launch_bounds__(128, 4)
wgemm64(const __nv_bfloat16* __restrict__ A, long lda,
        const __nv_bfloat16* __restrict__ B, long ldb,
        float* __restrict__ C, long ldc, int K) {
    extern __shared__ char smem[];
    const uint32_t sb = smem_u32(smem);
    const int tid = threadIdx.x, warp = tid >> 5;
    const int wm = warp >> 1, wn = warp & 1;    // 2x2 warps, 32x64 each
    const int bx = blockIdx.x, by = blockIdx.y;

    const __nv_bfloat16* Ab = A + (long)(by * 64) * lda;
    const __nv_bfloat16* Bb = B + (long)(bx * 128) * ldb;

    wmma::fragment<wmma::accumulator, 16, 16, 16, float> cf[2][4];
    #pragma unroll
    for (int i = 0; i < 2; i++)
        #pragma unroll
        for (int j = 0; j < 4; j++) wmma::fill_fragment(cf[i][j], 0.0f);

    const int KT = K >> 6;
    stage_t<128,64> (sb,          Ab,        lda);
    stage_t<128,128>(sb + ATIL64, Bb,        ldb);
    cp_commit();
    stage_t<128,64> (sb + STG64,          Ab + KSTG, lda);
    stage_t<128,128>(sb + STG64 + ATIL64, Bb + KSTG, ldb);
    cp_commit();

    for (int t = 0; t < KT; t++) {
        cp_wait<1>();
        __syncthreads();
        const char* buf = smem + (t & 1) * STG64;
        mma32((const __nv_bfloat16*)buf,
              (const __nv_bfloat16*)(buf + ATIL64), wm, wn, cf);
        __syncthreads();
        if (t + 2 < KT) {
            const uint32_t nb = sb + (t & 1) * STG64;   // (t+2)&1 == t&1
            stage_t<128,64> (nb,          Ab + (long)(t + 2) * KSTG, lda);
            stage_t<128,128>(nb + ATIL64, Bb + (long)(t + 2) * KSTG, ldb);
        }
        cp_commit();
    }

    #pragma unroll
    for (int i = 0; i < 2; i++)
        #pragma unroll
        for (int j = 0; j < 4; j++) {
            #pragma unroll
            for (int e = 0; e < cf[i][j].num_elements; e++)
                cf[i][j].x[e] = fmaxf(cf[i][j].x[e], 0.0f);
            float* Cp = C + (long)(by * 64 + wm * 32 + i * 16) * ldc
                          + (long)bx * 128 + wn * 64 + j * 16;
            wmma::store_matrix_sync(Cp, cf[i][j], ldc, wmma::mem_row_major);
        }
}

// ---------------------------------------------------------------------------
// Output kernel: symmetric (bx>=by), two-sync 3-buffer pipeline, 8 warps of
// 32x64. NEW: __launch_bounds__(256,2) caps regs at 128 so 2 CTAs/SM fit
// (smem 110.6K x 2 = 221K <= 228K). Cold `of` accumulators spill to local.
// ---------------------------------------------------------------------------
__global__ void __launch_bounds__(256, 2)
wout(const __nv_bfloat16* __restrict__ a,
     const float* __restrict__ som, const float* __restrict__ cum,
     const int* __restrict__ tsp, const int* __restrict__ Tp,
     float* __restrict__ out) {
    const int bx = blockIdx.x, by = blockIdx.y;
    if (bx < by) return;
    extern __shared__ char smem[];
    const uint32_t sb = smem_u32(smem);
    const int tid = threadIdx.x, warp = tid >> 5;
    const int wm = warp >> 1, wn = warp & 1;
    const int ts = *tsp, T = *Tp;
    const int s0 = ts - 1, nch = 2 * (T - ts + 1);

    const __nv_bfloat16* Arow = a + (long)(by * 128) * N2;
    const __nv_bfloat16* Brow = a + (long)(bx * 128) * N2;

    wmma::fragment<wmma::accumulator, 16, 16, 16, float> of[2][4], cf[2][4];
    #pragma unroll
    for (int i = 0; i < 2; i++)
        #pragma unroll
        for (int j = 0; j < 4; j++) {
            wmma::fill_fragment(of[i][j], 0.0f);
            wmma::fill_fragment(cf[i][j], 0.0f);
        }

    {   // prologue: chunks 0,1 (step s0, halves 0/1)
        long o0 = (long)s0 * H2W;
        stage_t<256,128>(sb,         Arow + o0, N2);
        stage_t<256,128>(sb + TILEB, Brow + o0, N2);
        cp_commit();
        stage_t<256,128>(sb + STG,         Arow + o0 + KSTG, N2);
        stage_t<256,128>(sb + STG + TILEB, Brow + o0 + KSTG, N2);
        cp_commit();
    }

    for (int g = 0; g < nch; g++) {
        cp_wait<1>();
        __syncthreads();
        const char* buf = smem + (g % 3) * STG;
        mma32((const __nv_bfloat16*)buf,
              (const __nv_bfloat16*)(buf + TILEB), wm, wn, cf);
        __syncthreads();
        if (g + 2 < nch) {
            int gn = g + 2;
            long off = (long)(s0 + (gn >> 1)) * H2W + (gn & 1) * KSTG;
            uint32_t nb = sb + (gn % 3) * STG;
            stage_t<256,128>(nb,         Arow + off, N2);
            stage_t<256,128>(nb + TILEB, Brow + off, N2);
        }
        cp_commit();
        if (g & 1) {   // step boundary: fold sigmoid, reset cf
            const float coef = som[s0 + (g >> 1)];
            #pragma unroll
            for (int i = 0; i < 2; i++)
                #pragma unroll
                for (int j = 0; j < 4; j++) {
                    #pragma unroll
                    for (int e = 0; e < cf[i][j].num_elements; e++) {
                        of[i][j].x[e] += coef * fast_sigmoid(cf[i][j].x[e]);
                        cf[i][j].x[e] = 0.0f;
                    }
                }
        }
    }

    const float inv = __fdividef(1.0f, cum[ts - 1]);
    #pragma unroll
    for (int i = 0; i < 2; i++)
        #pragma unroll
        for (int j = 0; j < 4; j++) {
            #pragma unroll
            for (int e = 0; e < of[i][j].num_elements; e++)
                of[i][j].x[e] *= inv;
            const int mg = by * 128 + wm * 32 + i * 16;
            const int ng = bx * 128 + wn * 64 + j * 16;
            wmma::store_matrix_sync(out + (long)mg * NROWS + ng, of[i][j],
                                    NROWS, wmma::mem_row_major);
            if (bx != by)
                wmma::store_matrix_sync(out + (long)ng * NROWS + mg, of[i][j],
                                        NROWS, wmma::mem_col_major);
        }
}

// ---------------------------------------------------------------------------
// Pre/post-processing
// ---------------------------------------------------------------------------
__global__ void cvt_bf16_kernel(const float* __restrict__ src,
                                __nv_bfloat16* __restrict__ dst, long n8) {
    long i = (long)blockIdx.x * blockDim.x + threadIdx.x;
    long stride = (long)gridDim.x * blockDim.x;
    for (; i < n8; i += stride) {
        float4 va = reinterpret_cast<const float4*>(src)[2 * i];
        float4 vb = reinterpret_cast<const float4*>(src)[2 * i + 1];
        uint4 o;
        __nv_bfloat162 h0 = __floats2bfloat162_rn(va.x, va.y);
        __nv_bfloat162 h1 = __floats2bfloat162_rn(va.z, va.w);
        __nv_bfloat162 h2 = __floats2bfloat162_rn(vb.x, vb.y);
        __nv_bfloat162 h3 = __floats2bfloat162_rn(vb.z, vb.w);
        o.x = *reinterpret_cast<uint32_t*>(&h0);
        o.y = *reinterpret_cast<uint32_t*>(&h1);
        o.z = *reinterpret_cast<uint32_t*>(&h2);
        o.w = *reinterpret_cast<uint32_t*>(&h3);
        reinterpret_cast<uint4*>(dst)[i] = o;
    }
}
// Transpose X^T (single big slab): Wt[n][k] = W[k][n] bf16
__global__ void transpose_w_kernel(const float* __restrict__ W,
                                   __nv_bfloat16* __restrict__ Wt, int K, int N) {
    for (long idx = blockIdx.x * blockDim.x + threadIdx.x; idx < (long)K * N;
         idx += (long)gridDim.x * blockDim.x) {
        long n = idx / K, k = idx % K;
        Wt[n * K + k] = __float2bfloat16(W[k * N + n]);
    }
}
// Merged W1/W2 slab transposes (y<NSTEP: W1 slab y; else W2 slab y-NSTEP)
__global__ void transpose_w2_kernel(const float* __restrict__ W1,
                                    const float* __restrict__ W2,
                                    __nv_bfloat16* __restrict__ W1t,
                                    __nv_bfloat16* __restrict__ W2t) {
    const int y = blockIdx.y;
    const float* Ws; __nv_bfloat16* Wd; int K, N;
    if (y < NSTEP) { Ws = W1 + (long)y * DIN * H1W; Wd = W1t + (long)y * DIN * H1W;
                     K = DIN; N = H1W; }
    else           { Ws = W2 + (long)(y - NSTEP) * H1W * H2W;
                     Wd = W2t + (long)(y - NSTEP) * H1W * H2W; K = H1W; N = H2W; }
    for (long idx = blockIdx.x * blockDim.x + threadIdx.x; idx < (long)K * N;
         idx += (long)gridDim.x * blockDim.x) {
        long n = idx / K, k = idx % K;
        Wd[n * K + k] = __float2bfloat16(Ws[k * N + n]);
    }
}
__global__ void mean_kernel(const float* __restrict__ H2, float* __restrict__ mean) {
    const int tx = threadIdx.x & 31;
    const int ty = threadIdx.x >> 5;
    const int col = blockIdx.x * 32 + tx;
    float s = 0.0f;
    for (int r = ty; r < NROWS; r += 8)
        s += H2[(long)r * N2 + col];
    __shared__ float red[8][32];
    red[ty][tx] = s;
    __syncthreads();
    if (ty == 0) {
        float t = 0.0f;
        #pragma unroll
        for (int i = 0; i < 8; i++) t += red[i][tx];
        mean[col] = t * (1.0f / NROWS);
    }
}
__global__ void center_kernel(const float* __restrict__ H2,
                              const float* __restrict__ mean,
                              __nv_bfloat16* __restrict__ a, long n) {
    long i = (long)blockIdx.x * blockDim.x + threadIdx.x;
    long st = (long)gridDim.x * blockDim.x;
    for (; i < n; i += st) {
        int c = (int)(i % N2);
        a[i] = __float2bfloat16(H2[i] - mean[c]);
    }
}

// ---------------------------------------------------------------------------
// Launch
// ---------------------------------------------------------------------------
extern "C" void kernel_launch(void* const* d_in, const int* in_sizes, int n_in,
                              void* d_out, int out_size) {
    const float* X   = (const float*)d_in[0];
    const float* adj = (const float*)d_in[1];
    const float* W1  = (const float*)d_in[2];
    const float* W2  = (const float*)d_in[3];
    const float* cum = (const float*)d_in[4];
    const float* som = (const float*)d_in[5];
    const int*   tsp = (const int*)d_in[6];
    const int*   Tp  = (const int*)d_in[7];
    float* out = (float*)d_out;
    (void)in_sizes; (void)n_in; (void)out_size;

    void *p_adjb, *p_xt, *p_ax, *p_w1t, *p_w2t, *p_h1, *p_t2t, *p_h2, *p_abf, *p_mean;
    cudaGetSymbolAddress(&p_adjb, g_adjb);
    cudaGetSymbolAddress(&p_xt,   g_Xt);
    cudaGetSymbolAddress(&p_ax,   g_AX);
    cudaGetSymbolAddress(&p_w1t,  g_W1t);
    cudaGetSymbolAddress(&p_w2t,  g_W2t);
    cudaGetSymbolAddress(&p_h1,   g_H1);
    cudaGetSymbolAddress(&p_t2t,  g_T2t);
    cudaGetSymbolAddress(&p_h2,   g_H2);
    cudaGetSymbolAddress(&p_abf,  g_abf);
    cudaGetSymbolAddress(&p_mean, g_mean);

    cudaFuncSetAttribute(wgemm<0>, cudaFuncAttributeMaxDynamicSharedMemorySize, GSM);
    cudaFuncSetAttribute(wgemm<1>, cudaFuncAttributeMaxDynamicSharedMemorySize, GSM);
    cudaFuncSetAttribute(wgemm<3>, cudaFuncAttributeMaxDynamicSharedMemorySize, GSM);
    cudaFuncSetAttribute(wgemm64,  cudaFuncAttributeMaxDynamicSharedMemorySize, GSM64);
    cudaFuncSetAttribute(wout,     cudaFuncAttributeMaxDynamicSharedMemorySize, GSM);

    // (1) adj -> bf16, (2) X^T, (3) merged W transposes, (4) AX ← profiled slot
    cvt_bf16_kernel<<<4096, 256>>>(adj, (__nv_bfloat16*)p_adjb, (long)NROWS * NROWS / 8);
    transpose_w_kernel<<<2048, 256>>>(X, (__nv_bfloat16*)p_xt, NROWS, DIN);
    transpose_w2_kernel<<<dim3(48, 2 * NSTEP), 256>>>(
        W1 + (size_t)DIN * H1W, W2 + (size_t)H1W * H2W,
        (__nv_bfloat16*)p_w1t, (__nv_bfloat16*)p_w2t);

    // AX = adj @ X                 [8192 x 512] bf16 (no relu)
    wgemm<3><<<dim3(DIN/128, NROWS/128), 128, GSM>>>(
        (const __nv_bfloat16*)p_adjb, NROWS, 0,
        (const __nv_bfloat16*)p_xt, NROWS, 0, DIN,
        (char*)p_ax, DIN, NROWS);

    // H1 = relu(AX @ W1slab)       [8192 x 1280] bf16
    wgemm<1><<<dim3(N1/128, NROWS/128), 128, GSM>>>(
        (const __nv_bfloat16*)p_ax, DIN, 0,
        (const __nv_bfloat16*)p_w1t, DIN, (long)H1W * DIN, H1W,
        (char*)p_h1, N1, DIN);

    // T2t = (H1slab @ W2slab)^T    [640 x 8192] bf16
    wgemm<0><<<dim3(N2/128, NROWS/128), 128, GSM>>>(
        (const __nv_bfloat16*)p_h1, N1, H1W,
        (const __nv_bfloat16*)p_w2t, H1W, (long)H2W * H1W, H2W,
        (char*)p_t2t, NROWS, H1W);

    // H2 = relu(adj @ T2)  [8192 x 640] f32 — 64-row tiles, 2-stage, 4 CTAs/SM
    wgemm64<<<dim3(N2/128, NROWS/64), 128, GSM64>>>(
        (const __nv_bfloat16*)p_adjb, NROWS,
        (const __nv_bfloat16*)p_t2t, NROWS,
        (float*)p_h2, N2, NROWS);

    mean_kernel<<<N2 / 32, 256>>>((const float*)p_h2, (float*)p_mean);
    center_kernel<<<4096, 256>>>((const float*)p_h2, (const float*)p_mean,
                                 (__nv_bfloat16*)p_abf, (long)NROWS * N2);

    wout<<<dim3(NROWS/128, NROWS/128), 256, GSM>>>(
        (const __nv_bfloat16*)p_abf, som, cum, tsp, Tp, out);
}

// round 15
// speedup vs baseline: 1.1240x; 1.0288x over previous
#include <cuda_runtime.h>
#include <cuda_bf16.h>
#include <mma.h>
#include <cstdint>

using namespace nvcuda;

// ---------------------------------------------------------------------------
// Problem shape
// ---------------------------------------------------------------------------
#define NROWS 8192
#define DIN   512
#define H1W   256
#define H2W   128
#define NSTEP 5
#define N1 (NSTEP*H1W)   // 1280
#define N2 (NSTEP*H2W)   // 640

#define KSTG  64
#define SLD   72                 // smem row stride in bf16 (144B)
#define TILEB (128*SLD*2)        // 18432 per 128x64 tile
#define STG   (2*TILEB)          // 36864 per stage (A+B)
#define GSM   (3*STG)            // 110592
#define CLD   129
// H2 variant: 64-row A tile, 2-stage pipeline, 4 CTAs/SM
#define ATIL64 (64*SLD*2)        // 9216
#define STG64  (ATIL64+TILEB)    // 27648
#define GSM64  (2*STG64)         // 55296 — 4 CTAs/SM

// ---------------------------------------------------------------------------
// Scratch (device globals)
// ---------------------------------------------------------------------------
__device__ __nv_bfloat16 g_adjb[(size_t)NROWS*NROWS];
__device__ __nv_bfloat16 g_Xt  [(size_t)DIN*NROWS];      // X^T bf16
__device__ __nv_bfloat16 g_AX  [(size_t)NROWS*DIN];      // adj@X bf16
__device__ __nv_bfloat16 g_W1t [(size_t)NSTEP*H1W*DIN];  // [s][n][k]
__device__ __nv_bfloat16 g_W2t [(size_t)NSTEP*H2W*H1W];  // [s][n][k]
__device__ __nv_bfloat16 g_H1  [(size_t)NROWS*N1];       // relu(AX@W1) bf16
__device__ __nv_bfloat16 g_T2t [(size_t)N2*NROWS];       // (H1@W2)^T bf16
__device__ float         g_H2  [(size_t)NROWS*N2];       // relu(adj@T2) f32
__device__ __nv_bfloat16 g_abf [(size_t)NROWS*N2];       // centered a bf16
__device__ float         g_mean[N2];

// ---------------------------------------------------------------------------
// Helpers
// ---------------------------------------------------------------------------
static __device__ __forceinline__ void cp16(uint32_t sdst, const void* g) {
    asm volatile("cp.async.cg.shared.global [%0], [%1], 16;"
                 :: "r"(sdst), "l"(g) : "memory");
}
static __device__ __forceinline__ void cp_commit() {
    asm volatile("cp.async.commit_group;" ::: "memory");
}
template <int N>
static __device__ __forceinline__ void cp_wait() {
    asm volatile("cp.async.wait_group %0;" :: "n"(N) : "memory");
}
static __device__ __forceinline__ uint32_t smem_u32(const void* p) {
    uint32_t a;
    asm("{ .reg .u64 t; cvta.to.shared.u64 t, %1; cvt.u32.u64 %0, t; }"
        : "=r"(a) : "l"(p));
    return a;
}
// Poly for |x|<0.25 (abs err < 2e-8), per-element exact fallback otherwise.
static __device__ __forceinline__ float fast_sigmoid(float x) {
    float ax = fabsf(x);
    float x2 = x * x;
    float p = 0.5f + x * (0.25f + x2 * (-0.0208333333f + x2 * 0.00208333333f));
    if (ax >= 0.25f) p = __fdividef(1.0f, 1.0f + __expf(-x));
    return p;
}

// Stage an NRxKSTG bf16 tile (row stride SLD); NT = threads in CTA.
template <int NT, int NR>
static __device__ __forceinline__ void stage_t(uint32_t sdst,
                                               const __nv_bfloat16* __restrict__ src,
                                               long ld) {
    const int t = threadIdx.x;
    #pragma unroll
    for (int i = 0; i < NR * 8 / NT; i++) {
        int c = t + i * NT;
        int row = c >> 3, col = c & 7;
        cp16(sdst + row * (SLD * 2) + col * 16, src + (long)row * ld + col * 8);
    }
}

// 64x64 warp tile over one 64-K chunk
template <typename FragC>
static __device__ __forceinline__ void mma64(const __nv_bfloat16* As,
                                             const __nv_bfloat16* Bs,
                                             int wm, int wn, FragC (&cf)[4][4]) {
    #pragma unroll
    for (int kk = 0; kk < KSTG; kk += 16) {
        wmma::fragment<wmma::matrix_a, 16, 16, 16, __nv_bfloat16, wmma::row_major> af[4];
        wmma::fragment<wmma::matrix_b, 16, 16, 16, __nv_bfloat16, wmma::col_major> bf[4];
        #pragma unroll
        for (int i = 0; i < 4; i++)
            wmma::load_matrix_sync(af[i], As + (wm * 64 + i * 16) * SLD + kk, SLD);
        #pragma unroll
        for (int j = 0; j < 4; j++)
            wmma::load_matrix_sync(bf[j], Bs + (wn * 64 + j * 16) * SLD + kk, SLD);
        #pragma unroll
        for (int i = 0; i < 4; i++)
            #pragma unroll
            for (int j = 0; j < 4; j++)
                wmma::mma_sync(cf[i][j], af[i], bf[j], cf[i][j]);
    }
}

// 32x64 warp tile over one 64-K chunk
template <typename FragC>
static __device__ __forceinline__ void mma32(const __nv_bfloat16* As,
                                             const __nv_bfloat16* Bs,
                                             int wm, int wn, FragC (&cf)[2][4]) {
    #pragma unroll
    for (int kk = 0; kk < KSTG; kk += 16) {
        wmma::fragment<wmma::matrix_a, 16, 16, 16, __nv_bfloat16, wmma::row_major> af[2];
        wmma::fragment<wmma::matrix_b, 16, 16, 16, __nv_bfloat16, wmma::col_major> bf[4];
        #pragma unroll
        for (int i = 0; i < 2; i++)
            wmma::load_matrix_sync(af[i], As + (wm * 32 + i * 16) * SLD + kk, SLD);
        #pragma unroll
        for (int j = 0; j < 4; j++)
            wmma::load_matrix_sync(bf[j], Bs + (wn * 64 + j * 16) * SLD + kk, SLD);
        #pragma unroll
        for (int i = 0; i < 2; i++)
            #pragma unroll
            for (int j = 0; j < 4; j++)
                wmma::mma_sync(cf[i][j], af[i], bf[j], cf[i][j]);
    }
}

// ---------------------------------------------------------------------------
// 3-stage pipelined GEMM, single-barrier loop with prefetch AFTER mma:
// at sync(t) every thread finished mma(t-1), so staging (t+2)%3 == (t-1)%3
// is race-free. C = op(A[M,K] @ B[N,K]^T). CTA 128x128, 4 warps, 64x64 tiles.
// EPI: 0 = bf16 transposed, 1 = bf16 row + relu, 3 = bf16 row (no relu)
// ---------------------------------------------------------------------------
template <int EPI>
__global__ void __launch_bounds__(128)
wgemm(const __nv_bfloat16* __restrict__ A, long lda, long aSlabCol,
      const __nv_bfloat16* __restrict__ B, long ldb, long bSlabStride, int outSlabN,
      char* __restrict__ Cv, long ldc, int K) {
    extern __shared__ char smem[];
    const uint32_t sb = smem_u32(smem);
    const int tid = threadIdx.x, warp = tid >> 5;
    const int wm = warp >> 1, wn = warp & 1;    // 2x2 warps, 64x64 each
    const int bx = blockIdx.x, by = blockIdx.y;

    const int slab = (bx * 128) / outSlabN;
    const __nv_bfloat16* Ab = A + (long)(by * 128) * lda + (long)slab * aSlabCol;
    const __nv_bfloat16* Bb = B + (long)slab * bSlabStride
                                + (long)((bx * 128) % outSlabN) * ldb;

    wmma::fragment<wmma::accumulator, 16, 16, 16, float> cf[4][4];
    #pragma unroll
    for (int i = 0; i < 4; i++)
        #pragma unroll
        for (int j = 0; j < 4; j++) wmma::fill_fragment(cf[i][j], 0.0f);

    const int KT = K >> 6;
    // prologue: stages 0, 1
    stage_t<128,128>(sb,         Ab,        lda);
    stage_t<128,128>(sb + TILEB, Bb,        ldb);
    cp_commit();
    stage_t<128,128>(sb + STG,         Ab + KSTG, lda);
    stage_t<128,128>(sb + STG + TILEB, Bb + KSTG, ldb);
    cp_commit();

    for (int t = 0; t < KT; t++) {
        cp_wait<1>();
        __syncthreads();          // stage-t data visible; all finished mma(t-1)
        const char* buf = smem + (t % 3) * STG;
        mma64((const __nv_bfloat16*)buf,
              (const __nv_bfloat16*)(buf + TILEB), wm, wn, cf);
        if (t + 2 < KT) {         // prefetch AFTER mma — buffer (t+2)%3 is free
            const uint32_t nb = sb + ((t + 2) % 3) * STG;
            stage_t<128,128>(nb,         Ab + (long)(t + 2) * KSTG, lda);
            stage_t<128,128>(nb + TILEB, Bb + (long)(t + 2) * KSTG, ldb);
        }
        cp_commit();              // uniform cadence
    }

    // bf16 outputs via smem Cs[128][129] f32 (reuses stage buffers)
    __syncthreads();              // other warps may still read last stage buffer
    float* Cs = (float*)smem;
    #pragma unroll
    for (int i = 0; i < 4; i++)
        #pragma unroll
        for (int j = 0; j < 4; j++)
            wmma::store_matrix_sync(Cs + (wm * 64 + i * 16) * CLD + wn * 64 + j * 16,
                                    cf[i][j], CLD, wmma::mem_row_major);
    __syncthreads();

    if (EPI == 0) {
        // transposed bf16: thread owns column n = tid, all 128 m values
        const int n = tid;
        __nv_bfloat16* dst = (__nv_bfloat16*)Cv + (long)(bx * 128 + n) * ldc
                                                + (long)by * 128;
        #pragma unroll
        for (int pass = 0; pass < 2; pass++) {
            uint32_t pk[32];
            #pragma unroll
            for (int k = 0; k < 32; k++) {
                int m = pass * 64 + 2 * k;
                __nv_bfloat162 h = __floats2bfloat162_rn(Cs[m * CLD + n],
                                                         Cs[(m + 1) * CLD + n]);
                pk[k] = *reinterpret_cast<uint32_t*>(&h);
            }
            #pragma unroll
            for (int i = 0; i < 8; i++)
                reinterpret_cast<uint4*>(dst + pass * 64)[i] =
                    *reinterpret_cast<uint4*>(pk + 4 * i);
        }
    } else {
        // row-major bf16: thread owns row m = tid (relu iff EPI==1)
        const int m = tid;
        __nv_bfloat16* dst = (__nv_bfloat16*)Cv + (long)(by * 128 + m) * ldc
                                                + (long)bx * 128;
        #pragma unroll
        for (int pass = 0; pass < 2; pass++) {
            uint32_t pk[32];
            #pragma unroll
            for (int k = 0; k < 32; k++) {
                int c = pass * 64 + 2 * k;
                float a = Cs[m * CLD + c];
                float b = Cs[m * CLD + c + 1];
                if (EPI == 1) { a = fmaxf(a, 0.0f); b = fmaxf(b, 0.0f); }
                __nv_bfloat162 h = __floats2bfloat162_rn(a, b);
                pk[k] = *reinterpret_cast<uint32_t*>(&h);
            }
            #pragma unroll
            for (int i = 0; i < 8; i++)
                reinterpret_cast<uint4*>(dst + pass * 64)[i] =
                    *reinterpret_cast<uint4*>(pk + 4 * i);
        }
    }
}

// ---------------------------------------------------------------------------
// H2 variant: CTA 64x128, 4 warps of 32x64, 2-stage pipeline, 4 CTAs/SM,
// single-barrier loop. f32 row-major + relu output (no smem reuse after loop).
// ---------------------------------------------------------------------------
__global__ void __launch_bounds__(128, 4)
wgemm64(const __nv_bfloat16* __restrict__ A, long lda,
        const __nv_bfloat16* __restrict__ B, long ldb,
        float* __restrict__ C, long ldc, int K) {
    extern __shared__ char smem[];
    const uint32_t sb = smem_u32(smem);
    const int tid = threadIdx.x, warp = tid >> 5;
    const int wm = warp >> 1, wn = warp & 1;    // 2x2 warps, 32x64 each
    const int bx = blockIdx.x, by = blockIdx.y;

    const __nv_bfloat16* Ab = A + (long)(by * 64) * lda;
    const __nv_bfloat16* Bb = B + (long)(bx * 128) * ldb;

    wmma::fragment<wmma::accumulator, 16, 16, 16, float> cf[2][4];
    #pragma unroll
    for (int i = 0; i < 2; i++)
        #pragma unroll
        for (int j = 0; j < 4; j++) wmma::fill_fragment(cf[i][j], 0.0f);

    const int KT = K >> 6;
    stage_t<128,64> (sb,          Ab,        lda);
    stage_t<128,128>(sb + ATIL64, Bb,        ldb);
    cp_commit();
    stage_t<128,64> (sb + STG64,          Ab + KSTG, lda);
    stage_t<128,128>(sb + STG64 + ATIL64, Bb + KSTG, ldb);
    cp_commit();

    for (int t = 0; t < KT; t++) {
        cp_wait<1>();
        __syncthreads();
        const char* buf = smem + (t & 1) * STG64;
        mma32((const __nv_bfloat16*)buf,
              (const __nv_bfloat16*)(buf + ATIL64), wm, wn, cf);
        if (t + 2 < KT) {
            const uint32_t nb = sb + (t & 1) * STG64;   // (t+2)&1 == t&1
            stage_t<128,64> (nb,          Ab + (long)(t + 2) * KSTG, lda);
            stage_t<128,128>(nb + ATIL64, Bb + (long)(t + 2) * KSTG, ldb);
        }
        cp_commit();
    }

    #pragma unroll
    for (int i = 0; i < 2; i++)
        #pragma unroll
        for (int j = 0; j < 4; j++) {
            #pragma unroll
            for (int e = 0; e < cf[i][j].num_elements; e++)
                cf[i][j].x[e] = fmaxf(cf[i][j].x[e], 0.0f);
            float* Cp = C + (long)(by * 64 + wm * 32 + i * 16) * ldc
                          + (long)bx * 128 + wn * 64 + j * 16;
            wmma::store_matrix_sync(Cp, cf[i][j], ldc, wmma::mem_row_major);
        }
}

// ---------------------------------------------------------------------------
// Output kernel: symmetric (bx>=by), single-barrier 3-buffer pipeline,
// 8 warps of 32x64, 2 CTAs/SM via launch_bounds(256,2), sigmoid fold,
// mirrored stores.
// ---------------------------------------------------------------------------
__global__ void __launch_bounds__(256, 2)
wout(const __nv_bfloat16* __restrict__ a,
     const float* __restrict__ som, const float* __restrict__ cum,
     const int* __restrict__ tsp, const int* __restrict__ Tp,
     float* __restrict__ out) {
    const int bx = blockIdx.x, by = blockIdx.y;
    if (bx < by) return;
    extern __shared__ char smem[];
    const uint32_t sb = smem_u32(smem);
    const int tid = threadIdx.x, warp = tid >> 5;
    const int wm = warp >> 1, wn = warp & 1;
    const int ts = *tsp, T = *Tp;
    const int s0 = ts - 1, nch = 2 * (T - ts + 1);

    const __nv_bfloat16* Arow = a + (long)(by * 128) * N2;
    const __nv_bfloat16* Brow = a + (long)(bx * 128) * N2;

    wmma::fragment<wmma::accumulator, 16, 16, 16, float> of[2][4], cf[2][4];
    #pragma unroll
    for (int i = 0; i < 2; i++)
        #pragma unroll
        for (int j = 0; j < 4; j++) {
            wmma::fill_fragment(of[i][j], 0.0f);
            wmma::fill_fragment(cf[i][j], 0.0f);
        }

    {   // prologue: chunks 0,1 (step s0, halves 0/1)
        long o0 = (long)s0 * H2W;
        stage_t<256,128>(sb,         Arow + o0, N2);
        stage_t<256,128>(sb + TILEB, Brow + o0, N2);
        cp_commit();
        stage_t<256,128>(sb + STG,         Arow + o0 + KSTG, N2);
        stage_t<256,128>(sb + STG + TILEB, Brow + o0 + KSTG, N2);
        cp_commit();
    }

    for (int g = 0; g < nch; g++) {
        cp_wait<1>();
        __syncthreads();
        const char* buf = smem + (g % 3) * STG;
        mma32((const __nv_bfloat16*)buf,
              (const __nv_bfloat16*)(buf + TILEB), wm, wn, cf);
        if (g + 2 < nch) {
            int gn = g + 2;
            long off = (long)(s0 + (gn >> 1)) * H2W + (gn & 1) * KSTG;
            uint32_t nb = sb + (gn % 3) * STG;
            stage_t<256,128>(nb,         Arow + off, N2);
            stage_t<256,128>(nb + TILEB, Brow + off, N2);
        }
        cp_commit();
        if (g & 1) {   // step boundary: fold sigmoid, reset cf
            const float coef = som[s0 + (g >> 1)];
            #pragma unroll
            for (int i = 0; i < 2; i++)
                #pragma unroll
                for (int j = 0; j < 4; j++) {
                    #pragma unroll
                    for (int e = 0; e < cf[i][j].num_elements; e++) {
                        of[i][j].x[e] += coef * fast_sigmoid(cf[i][j].x[e]);
                        cf[i][j].x[e] = 0.0f;
                    }
                }
        }
    }

    const float inv = __fdividef(1.0f, cum[ts - 1]);
    #pragma unroll
    for (int i = 0; i < 2; i++)
        #pragma unroll
        for (int j = 0; j < 4; j++) {
            #pragma unroll
            for (int e = 0; e < of[i][j].num_elements; e++)
                of[i][j].x[e] *= inv;
            const int mg = by * 128 + wm * 32 + i * 16;
            const int ng = bx * 128 + wn * 64 + j * 16;
            wmma::store_matrix_sync(out + (long)mg * NROWS + ng, of[i][j],
                                    NROWS, wmma::mem_row_major);
            if (bx != by)
                wmma::store_matrix_sync(out + (long)ng * NROWS + mg, of[i][j],
                                        NROWS, wmma::mem_col_major);
        }
}

// ---------------------------------------------------------------------------
// Pre/post-processing
// ---------------------------------------------------------------------------
__global__ void cvt_bf16_kernel(const float* __restrict__ src,
                                __nv_bfloat16* __restrict__ dst, long n8) {
    long i = (long)blockIdx.x * blockDim.x + threadIdx.x;
    long stride = (long)gridDim.x * blockDim.x;
    for (; i < n8; i += stride) {
        float4 va = reinterpret_cast<const float4*>(src)[2 * i];
        float4 vb = reinterpret_cast<const float4*>(src)[2 * i + 1];
        uint4 o;
        __nv_bfloat162 h0 = __floats2bfloat162_rn(va.x, va.y);
        __nv_bfloat162 h1 = __floats2bfloat162_rn(va.z, va.w);
        __nv_bfloat162 h2 = __floats2bfloat162_rn(vb.x, vb.y);
        __nv_bfloat162 h3 = __floats2bfloat162_rn(vb.z, vb.w);
        o.x = *reinterpret_cast<uint32_t*>(&h0);
        o.y = *reinterpret_cast<uint32_t*>(&h1);
        o.z = *reinterpret_cast<uint32_t*>(&h2);
        o.w = *reinterpret_cast<uint32_t*>(&h3);
        reinterpret_cast<uint4*>(dst)[i] = o;
    }
}
// Transpose X^T (single big slab): Wt[n][k] = W[k][n] bf16
__global__ void transpose_w_kernel(const float* __restrict__ W,
                                   __nv_bfloat16* __restrict__ Wt, int K, int N) {
    for (long idx = blockIdx.x * blockDim.x + threadIdx.x; idx < (long)K * N;
         idx += (long)gridDim.x * blockDim.x) {
        long n = idx / K, k = idx % K;
        Wt[n * K + k] = __float2bfloat16(W[k * N + n]);
    }
}
// Merged W1/W2 slab transposes (y<NSTEP: W1 slab y; else W2 slab y-NSTEP)
__global__ void transpose_w2_kernel(const float* __restrict__ W1,
                                    const float* __restrict__ W2,
                                    __nv_bfloat16* __restrict__ W1t,
                                    __nv_bfloat16* __restrict__ W2t) {
    const int y = blockIdx.y;
    const float* Ws; __nv_bfloat16* Wd; int K, N;
    if (y < NSTEP) { Ws = W1 + (long)y * DIN * H1W; Wd = W1t + (long)y * DIN * H1W;
                     K = DIN; N = H1W; }
    else           { Ws = W2 + (long)(y - NSTEP) * H1W * H2W;
                     Wd = W2t + (long)(y - NSTEP) * H1W * H2W; K = H1W; N = H2W; }
    for (long idx = blockIdx.x * blockDim.x + threadIdx.x; idx < (long)K * N;
         idx += (long)gridDim.x * blockDim.x) {
        long n = idx / K, k = idx % K;
        Wd[n * K + k] = __float2bfloat16(Ws[k * N + n]);
    }
}
__global__ void mean_kernel(const float* __restrict__ H2, float* __restrict__ mean) {
    const int tx = threadIdx.x & 31;
    const int ty = threadIdx.x >> 5;
    const int col = blockIdx.x * 32 + tx;
    float s = 0.0f;
    for (int r = ty; r < NROWS; r += 8)
        s += H2[(long)r * N2 + col];
    __shared__ float red[8][32];
    red[ty][tx] = s;
    __syncthreads();
    if (ty == 0) {
        float t = 0.0f;
        #pragma unroll
        for (int i = 0; i < 8; i++) t += red[i][tx];
        mean[col] = t * (1.0f / NROWS);
    }
}
__global__ void center_kernel(const float* __restrict__ H2,
                              const float* __restrict__ mean,
                              __nv_bfloat16* __restrict__ a, long n) {
    long i = (long)blockIdx.x * blockDim.x + threadIdx.x;
    long st = (long)gridDim.x * blockDim.x;
    for (; i < n; i += st) {
        int c = (int)(i % N2);
        a[i] = __float2bfloat16(H2[i] - mean[c]);
    }
}

// ---------------------------------------------------------------------------
// Launch
// ---------------------------------------------------------------------------
extern "C" void kernel_launch(void* const* d_in, const int* in_sizes, int n_in,
                              void* d_out, int out_size) {
    const float* X   = (const float*)d_in[0];
    const float* adj = (const float*)d_in[1];
    const float* W1  = (const float*)d_in[2];
    const float* W2  = (const float*)d_in[3];
    const float* cum = (const float*)d_in[4];
    const float* som = (const float*)d_in[5];
    const int*   tsp = (const int*)d_in[6];
    const int*   Tp  = (const int*)d_in[7];
    float* out = (float*)d_out;
    (void)in_sizes; (void)n_in; (void)out_size;

    void *p_adjb, *p_xt, *p_ax, *p_w1t, *p_w2t, *p_h1, *p_t2t, *p_h2, *p_abf, *p_mean;
    cudaGetSymbolAddress(&p_adjb, g_adjb);
    cudaGetSymbolAddress(&p_xt,   g_Xt);
    cudaGetSymbolAddress(&p_ax,   g_AX);
    cudaGetSymbolAddress(&p_w1t,  g_W1t);
    cudaGetSymbolAddress(&p_w2t,  g_W2t);
    cudaGetSymbolAddress(&p_h1,   g_H1);
    cudaGetSymbolAddress(&p_t2t,  g_T2t);
    cudaGetSymbolAddress(&p_h2,   g_H2);
    cudaGetSymbolAddress(&p_abf,  g_abf);
    cudaGetSymbolAddress(&p_mean, g_mean);

    cudaFuncSetAttribute(wgemm<0>, cudaFuncAttributeMaxDynamicSharedMemorySize, GSM);
    cudaFuncSetAttribute(wgemm<1>, cudaFuncAttributeMaxDynamicSharedMemorySize, GSM);
    cudaFuncSetAttribute(wgemm<3>, cudaFuncAttributeMaxDynamicSharedMemorySize, GSM);
    cudaFuncSetAttribute(wgemm64,  cudaFuncAttributeMaxDynamicSharedMemorySize, GSM64);
    cudaFuncSetAttribute(wout,     cudaFuncAttributeMaxDynamicSharedMemorySize, GSM);

    // (1) adj -> bf16, (2) X^T, (3) merged W transposes, (4) AX ← profiled slot
    cvt_bf16_kernel<<<4096, 256>>>(adj, (__nv_bfloat16*)p_adjb, (long)NROWS * NROWS / 8);
    transpose_w_kernel<<<2048, 256>>>(X, (__nv_bfloat16*)p_xt, NROWS, DIN);
    transpose_w2_kernel<<<dim3(48, 2 * NSTEP), 256>>>(
        W1 + (size_t)DIN * H1W, W2 + (size_t)H1W * H2W,
        (__nv_bfloat16*)p_w1t, (__nv_bfloat16*)p_w2t);

    // AX = adj @ X                 [8192 x 512] bf16 (no relu)
    wgemm<3><<<dim3(DIN/128, NROWS/128), 128, GSM>>>(
        (const __nv_bfloat16*)p_adjb, NROWS, 0,
        (const __nv_bfloat16*)p_xt, NROWS, 0, DIN,
        (char*)p_ax, DIN, NROWS);

    // H1 = relu(AX @ W1slab)       [8192 x 1280] bf16
    wgemm<1><<<dim3(N1/128, NROWS/128), 128, GSM>>>(
        (const __nv_bfloat16*)p_ax, DIN, 0,
        (const __nv_bfloat16*)p_w1t, DIN, (long)H1W * DIN, H1W,
        (char*)p_h1, N1, DIN);

    // T2t = (H1slab @ W2slab)^T    [640 x 8192] bf16
    wgemm<0><<<dim3(N2/128, NROWS/128), 128, GSM>>>(
        (const __nv_bfloat16*)p_h1, N1, H1W,
        (const __nv_bfloat16*)p_w2t, H1W, (long)H2W * H1W, H2W,
        (char*)p_t2t, NROWS, H1W);

    // H2 = relu(adj @ T2)  [8192 x 640] f32 — 64-row tiles, 2-stage, 4 CTAs/SM
    wgemm64<<<dim3(N2/128, NROWS/64), 128, GSM64>>>(
        (const __nv_bfloat16*)p_adjb, NROWS,
        (const __nv_bfloat16*)p_t2t, NROWS,
        (float*)p_h2, N2, NROWS);

    mean_kernel<<<N2 / 32, 256>>>((const float*)p_h2, (float*)p_mean);
    center_kernel<<<4096, 256>>>((const float*)p_h2, (const float*)p_mean,
                                 (__nv_bfloat16*)p_abf, (long)NROWS * N2);

    wout<<<dim3(NROWS/128, NROWS/128), 256, GSM>>>(
        (const __nv_bfloat16*)p_abf, som, cum, tsp, Tp, out);
}

// round 16
// speedup vs baseline: 1.1533x; 1.0261x over previous
#include <cuda_runtime.h>
#include <cuda_bf16.h>
#include <mma.h>
#include <cstdint>

using namespace nvcuda;

// ---------------------------------------------------------------------------
// Problem shape
// ---------------------------------------------------------------------------
#define NROWS 8192
#define DIN   512
#define H1W   256
#define H2W   128
#define NSTEP 5
#define N1 (NSTEP*H1W)   // 1280
#define N2 (NSTEP*H2W)   // 640

#define KSTG  64
#define SLD   72                 // smem row stride in bf16 (144B)
#define TILEB (128*SLD*2)        // 18432 per 128x64 tile
#define STG   (2*TILEB)          // 36864 per stage (A+B)
#define GSM   (3*STG)            // 110592
#define CLD   129
// 64-row-A variant (H1 + H2): 2-stage pipeline, 4 CTAs/SM
#define ATIL64 (64*SLD*2)        // 9216
#define STG64  (ATIL64+TILEB)    // 27648
#define GSM64  (2*STG64)         // 55296 — 4 CTAs/SM

// ---------------------------------------------------------------------------
// Scratch (device globals)
// ---------------------------------------------------------------------------
__device__ __nv_bfloat16 g_adjb[(size_t)NROWS*NROWS];
__device__ __nv_bfloat16 g_Xt  [(size_t)DIN*NROWS];      // X^T bf16
__device__ __nv_bfloat16 g_AX  [(size_t)NROWS*DIN];      // adj@X bf16
__device__ __nv_bfloat16 g_W1t [(size_t)NSTEP*H1W*DIN];  // [s][n][k]
__device__ __nv_bfloat16 g_W2t [(size_t)NSTEP*H2W*H1W];  // [s][n][k]
__device__ __nv_bfloat16 g_H1  [(size_t)NROWS*N1];       // relu(AX@W1) bf16
__device__ __nv_bfloat16 g_T2t [(size_t)N2*NROWS];       // (H1@W2)^T bf16
__device__ float         g_H2  [(size_t)NROWS*N2];       // relu(adj@T2) f32
__device__ __nv_bfloat16 g_abf [(size_t)NROWS*N2];       // centered a bf16
__device__ float         g_mean[N2];

// ---------------------------------------------------------------------------
// Helpers
// ---------------------------------------------------------------------------
static __device__ __forceinline__ void cp16(uint32_t sdst, const void* g) {
    asm volatile("cp.async.cg.shared.global [%0], [%1], 16;"
                 :: "r"(sdst), "l"(g) : "memory");
}
static __device__ __forceinline__ void cp_commit() {
    asm volatile("cp.async.commit_group;" ::: "memory");
}
template <int N>
static __device__ __forceinline__ void cp_wait() {
    asm volatile("cp.async.wait_group %0;" :: "n"(N) : "memory");
}
static __device__ __forceinline__ uint32_t smem_u32(const void* p) {
    uint32_t a;
    asm("{ .reg .u64 t; cvta.to.shared.u64 t, %1; cvt.u32.u64 %0, t; }"
        : "=r"(a) : "l"(p));
    return a;
}
// Poly for |x|<0.25 (abs err < 2e-8), per-element exact fallback otherwise.
static __device__ __forceinline__ float fast_sigmoid(float x) {
    float ax = fabsf(x);
    float x2 = x * x;
    float p = 0.5f + x * (0.25f + x2 * (-0.0208333333f + x2 * 0.00208333333f));
    if (ax >= 0.25f) p = __fdividef(1.0f, 1.0f + __expf(-x));
    return p;
}

// Stage an NRxKSTG bf16 tile (row stride SLD); NT = threads in CTA.
template <int NT, int NR>
static __device__ __forceinline__ void stage_t(uint32_t sdst,
                                               const __nv_bfloat16* __restrict__ src,
                                               long ld) {
    const int t = threadIdx.x;
    #pragma unroll
    for (int i = 0; i < NR * 8 / NT; i++) {
        int c = t + i * NT;
        int row = c >> 3, col = c & 7;
        cp16(sdst + row * (SLD * 2) + col * 16, src + (long)row * ld + col * 8);
    }
}

// 64x64 warp tile over one 64-K chunk
template <typename FragC>
static __device__ __forceinline__ void mma64(const __nv_bfloat16* As,
                                             const __nv_bfloat16* Bs,
                                             int wm, int wn, FragC (&cf)[4][4]) {
    #pragma unroll
    for (int kk = 0; kk < KSTG; kk += 16) {
        wmma::fragment<wmma::matrix_a, 16, 16, 16, __nv_bfloat16, wmma::row_major> af[4];
        wmma::fragment<wmma::matrix_b, 16, 16, 16, __nv_bfloat16, wmma::col_major> bf[4];
        #pragma unroll
        for (int i = 0; i < 4; i++)
            wmma::load_matrix_sync(af[i], As + (wm * 64 + i * 16) * SLD + kk, SLD);
        #pragma unroll
        for (int j = 0; j < 4; j++)
            wmma::load_matrix_sync(bf[j], Bs + (wn * 64 + j * 16) * SLD + kk, SLD);
        #pragma unroll
        for (int i = 0; i < 4; i++)
            #pragma unroll
            for (int j = 0; j < 4; j++)
                wmma::mma_sync(cf[i][j], af[i], bf[j], cf[i][j]);
    }
}

// 32x64 warp tile over one 64-K chunk
template <typename FragC>
static __device__ __forceinline__ void mma32(const __nv_bfloat16* As,
                                             const __nv_bfloat16* Bs,
                                             int wm, int wn, FragC (&cf)[2][4]) {
    #pragma unroll
    for (int kk = 0; kk < KSTG; kk += 16) {
        wmma::fragment<wmma::matrix_a, 16, 16, 16, __nv_bfloat16, wmma::row_major> af[2];
        wmma::fragment<wmma::matrix_b, 16, 16, 16, __nv_bfloat16, wmma::col_major> bf[4];
        #pragma unroll
        for (int i = 0; i < 2; i++)
            wmma::load_matrix_sync(af[i], As + (wm * 32 + i * 16) * SLD + kk, SLD);
        #pragma unroll
        for (int j = 0; j < 4; j++)
            wmma::load_matrix_sync(bf[j], Bs + (wn * 64 + j * 16) * SLD + kk, SLD);
        #pragma unroll
        for (int i = 0; i < 2; i++)
            #pragma unroll
            for (int j = 0; j < 4; j++)
                wmma::mma_sync(cf[i][j], af[i], bf[j], cf[i][j]);
    }
}

// ---------------------------------------------------------------------------
// 3-stage pipelined GEMM, single-barrier loop with prefetch AFTER mma.
// CTA 128x128, 4 warps, 64x64 tiles.
// EPI: 0 = bf16 transposed, 3 = bf16 row (no relu)
// ---------------------------------------------------------------------------
template <int EPI>
__global__ void __launch_bounds__(128)
wgemm(const __nv_bfloat16* __restrict__ A, long lda, long aSlabCol,
      const __nv_bfloat16* __restrict__ B, long ldb, long bSlabStride, int outSlabN,
      char* __restrict__ Cv, long ldc, int K) {
    extern __shared__ char smem[];
    const uint32_t sb = smem_u32(smem);
    const int tid = threadIdx.x, warp = tid >> 5;
    const int wm = warp >> 1, wn = warp & 1;    // 2x2 warps, 64x64 each
    const int bx = blockIdx.x, by = blockIdx.y;

    const int slab = (bx * 128) / outSlabN;
    const __nv_bfloat16* Ab = A + (long)(by * 128) * lda + (long)slab * aSlabCol;
    const __nv_bfloat16* Bb = B + (long)slab * bSlabStride
                                + (long)((bx * 128) % outSlabN) * ldb;

    wmma::fragment<wmma::accumulator, 16, 16, 16, float> cf[4][4];
    #pragma unroll
    for (int i = 0; i < 4; i++)
        #pragma unroll
        for (int j = 0; j < 4; j++) wmma::fill_fragment(cf[i][j], 0.0f);

    const int KT = K >> 6;
    stage_t<128,128>(sb,         Ab,        lda);
    stage_t<128,128>(sb + TILEB, Bb,        ldb);
    cp_commit();
    stage_t<128,128>(sb + STG,         Ab + KSTG, lda);
    stage_t<128,128>(sb + STG + TILEB, Bb + KSTG, ldb);
    cp_commit();

    for (int t = 0; t < KT; t++) {
        cp_wait<1>();
        __syncthreads();          // stage-t visible; all finished mma(t-1)
        const char* buf = smem + (t % 3) * STG;
        mma64((const __nv_bfloat16*)buf,
              (const __nv_bfloat16*)(buf + TILEB), wm, wn, cf);
        if (t + 2 < KT) {         // buffer (t+2)%3 == (t-1)%3 is free
            const uint32_t nb = sb + ((t + 2) % 3) * STG;
            stage_t<128,128>(nb,         Ab + (long)(t + 2) * KSTG, lda);
            stage_t<128,128>(nb + TILEB, Bb + (long)(t + 2) * KSTG, ldb);
        }
        cp_commit();
    }

    // bf16 outputs via smem Cs[128][129] f32 (reuses stage buffers)
    __syncthreads();
    float* Cs = (float*)smem;
    #pragma unroll
    for (int i = 0; i < 4; i++)
        #pragma unroll
        for (int j = 0; j < 4; j++)
            wmma::store_matrix_sync(Cs + (wm * 64 + i * 16) * CLD + wn * 64 + j * 16,
                                    cf[i][j], CLD, wmma::mem_row_major);
    __syncthreads();

    if (EPI == 0) {
        // transposed bf16: thread owns column n = tid, all 128 m values
        const int n = tid;
        __nv_bfloat16* dst = (__nv_bfloat16*)Cv + (long)(bx * 128 + n) * ldc
                                                + (long)by * 128;
        #pragma unroll
        for (int pass = 0; pass < 2; pass++) {
            uint32_t pk[32];
            #pragma unroll
            for (int k = 0; k < 32; k++) {
                int m = pass * 64 + 2 * k;
                __nv_bfloat162 h = __floats2bfloat162_rn(Cs[m * CLD + n],
                                                         Cs[(m + 1) * CLD + n]);
                pk[k] = *reinterpret_cast<uint32_t*>(&h);
            }
            #pragma unroll
            for (int i = 0; i < 8; i++)
                reinterpret_cast<uint4*>(dst + pass * 64)[i] =
                    *reinterpret_cast<uint4*>(pk + 4 * i);
        }
    } else {
        // row-major bf16 (no relu): thread owns row m = tid
        const int m = tid;
        __nv_bfloat16* dst = (__nv_bfloat16*)Cv + (long)(by * 128 + m) * ldc
                                                + (long)bx * 128;
        #pragma unroll
        for (int pass = 0; pass < 2; pass++) {
            uint32_t pk[32];
            #pragma unroll
            for (int k = 0; k < 32; k++) {
                int c = pass * 64 + 2 * k;
                __nv_bfloat162 h = __floats2bfloat162_rn(Cs[m * CLD + c],
                                                         Cs[m * CLD + c + 1]);
                pk[k] = *reinterpret_cast<uint32_t*>(&h);
            }
            #pragma unroll
            for (int i = 0; i < 8; i++)
                reinterpret_cast<uint4*>(dst + pass * 64)[i] =
                    *reinterpret_cast<uint4*>(pk + 4 * i);
        }
    }
}

// ---------------------------------------------------------------------------
// 64-row-A variant: CTA 64x128, 4 warps of 32x64, 2-stage pipeline, 4 CTAs/SM,
// single-barrier loop. Slab-aware B (for H1's per-step W1t blocks).
// EPI: 1 = bf16 row + relu (H1), 2 = f32 row + relu (H2)
// ---------------------------------------------------------------------------
template <int EPI>
__global__ void __launch_bounds__(128, 4)
wgemm64(const __nv_bfloat16* __restrict__ A, long lda,
        const __nv_bfloat16* __restrict__ B, long ldb, long bSlabStride, int outSlabN,
        char* __restrict__ Cv, long ldc, int K) {
    extern __shared__ char smem[];
    const uint32_t sb = smem_u32(smem);
    const int tid = threadIdx.x, warp = tid >> 5;
    const int wm = warp >> 1, wn = warp & 1;    // 2x2 warps, 32x64 each
    const int bx = blockIdx.x, by = blockIdx.y;

    const int slab = (bx * 128) / outSlabN;
    const __nv_bfloat16* Ab = A + (long)(by * 64) * lda;
    const __nv_bfloat16* Bb = B + (long)slab * bSlabStride
                                + (long)((bx * 128) % outSlabN) * ldb;

    wmma::fragment<wmma::accumulator, 16, 16, 16, float> cf[2][4];
    #pragma unroll
    for (int i = 0; i < 2; i++)
        #pragma unroll
        for (int j = 0; j < 4; j++) wmma::fill_fragment(cf[i][j], 0.0f);

    const int KT = K >> 6;
    stage_t<128,64> (sb,          Ab,        lda);
    stage_t<128,128>(sb + ATIL64, Bb,        ldb);
    cp_commit();
    stage_t<128,64> (sb + STG64,          Ab + KSTG, lda);
    stage_t<128,128>(sb + STG64 + ATIL64, Bb + KSTG, ldb);
    cp_commit();

    for (int t = 0; t < KT; t++) {
        cp_wait<1>();
        __syncthreads();
        const char* buf = smem + (t & 1) * STG64;
        mma32((const __nv_bfloat16*)buf,
              (const __nv_bfloat16*)(buf + ATIL64), wm, wn, cf);
        if (t + 2 < KT) {
            const uint32_t nb = sb + (t & 1) * STG64;   // (t+2)&1 == t&1
            stage_t<128,64> (nb,          Ab + (long)(t + 2) * KSTG, lda);
            stage_t<128,128>(nb + ATIL64, Bb + (long)(t + 2) * KSTG, ldb);
        }
        cp_commit();
    }

    if (EPI == 2) {
        #pragma unroll
        for (int i = 0; i < 2; i++)
            #pragma unroll
            for (int j = 0; j < 4; j++) {
                #pragma unroll
                for (int e = 0; e < cf[i][j].num_elements; e++)
                    cf[i][j].x[e] = fmaxf(cf[i][j].x[e], 0.0f);
                float* Cp = (float*)Cv + (long)(by * 64 + wm * 32 + i * 16) * ldc
                                       + (long)bx * 128 + wn * 64 + j * 16;
                wmma::store_matrix_sync(Cp, cf[i][j], ldc, wmma::mem_row_major);
            }
        return;
    }

    // EPI == 1: bf16 row-major + relu via smem Cs[64][129] f32
    __syncthreads();     // other warps may still read last stage buffer
    float* Cs = (float*)smem;
    #pragma unroll
    for (int i = 0; i < 2; i++)
        #pragma unroll
        for (int j = 0; j < 4; j++)
            wmma::store_matrix_sync(Cs + (wm * 32 + i * 16) * CLD + wn * 64 + j * 16,
                                    cf[i][j], CLD, wmma::mem_row_major);
    __syncthreads();

    const int m = tid >> 1, nb0 = (tid & 1) * 64;
    uint32_t pk[32];
    #pragma unroll
    for (int k = 0; k < 32; k++) {
        float a = fmaxf(Cs[m * CLD + nb0 + 2*k],     0.0f);
        float b = fmaxf(Cs[m * CLD + nb0 + 2*k + 1], 0.0f);
        __nv_bfloat162 h = __floats2bfloat162_rn(a, b);
        pk[k] = *reinterpret_cast<uint32_t*>(&h);
    }
    __nv_bfloat16* dst = (__nv_bfloat16*)Cv + (long)(by * 64 + m) * ldc
                                            + (long)bx * 128 + nb0;
    #pragma unroll
    for (int i = 0; i < 8; i++)
        reinterpret_cast<uint4*>(dst)[i] = *reinterpret_cast<uint4*>(pk + 4 * i);
}

// ---------------------------------------------------------------------------
// Output kernel: symmetric (bx>=by), single-barrier 3-buffer pipeline,
// 8 warps of 32x64, 2 CTAs/SM via launch_bounds(256,2), sigmoid fold,
// mirrored stores. (R15 config, unchanged.)
// ---------------------------------------------------------------------------
__global__ void __launch_bounds__(256, 2)
wout(const __nv_bfloat16* __restrict__ a,
     const float* __restrict__ som, const float* __restrict__ cum,
     const int* __restrict__ tsp, const int* __restrict__ Tp,
     float* __restrict__ out) {
    const int bx = blockIdx.x, by = blockIdx.y;
    if (bx < by) return;
    extern __shared__ char smem[];
    const uint32_t sb = smem_u32(smem);
    const int tid = threadIdx.x, warp = tid >> 5;
    const int wm = warp >> 1, wn = warp & 1;
    const int ts = *tsp, T = *Tp;
    const int s0 = ts - 1, nch = 2 * (T - ts + 1);

    const __nv_bfloat16* Arow = a + (long)(by * 128) * N2;
    const __nv_bfloat16* Brow = a + (long)(bx * 128) * N2;

    wmma::fragment<wmma::accumulator, 16, 16, 16, float> of[2][4], cf[2][4];
    #pragma unroll
    for (int i = 0; i < 2; i++)
        #pragma unroll
        for (int j = 0; j < 4; j++) {
            wmma::fill_fragment(of[i][j], 0.0f);
            wmma::fill_fragment(cf[i][j], 0.0f);
        }

    {   // prologue: chunks 0,1 (step s0, halves 0/1)
        long o0 = (long)s0 * H2W;
        stage_t<256,128>(sb,         Arow + o0, N2);
        stage_t<256,128>(sb + TILEB, Brow + o0, N2);
        cp_commit();
        stage_t<256,128>(sb + STG,         Arow + o0 + KSTG, N2);
        stage_t<256,128>(sb + STG + TILEB, Brow + o0 + KSTG, N2);
        cp_commit();
    }

    for (int g = 0; g < nch; g++) {
        cp_wait<1>();
        __syncthreads();
        const char* buf = smem + (g % 3) * STG;
        mma32((const __nv_bfloat16*)buf,
              (const __nv_bfloat16*)(buf + TILEB), wm, wn, cf);
        if (g + 2 < nch) {
            int gn = g + 2;
            long off = (long)(s0 + (gn >> 1)) * H2W + (gn & 1) * KSTG;
            uint32_t nb = sb + (gn % 3) * STG;
            stage_t<256,128>(nb,         Arow + off, N2);
            stage_t<256,128>(nb + TILEB, Brow + off, N2);
        }
        cp_commit();
        if (g & 1) {   // step boundary: fold sigmoid, reset cf
            const float coef = som[s0 + (g >> 1)];
            #pragma unroll
            for (int i = 0; i < 2; i++)
                #pragma unroll
                for (int j = 0; j < 4; j++) {
                    #pragma unroll
                    for (int e = 0; e < cf[i][j].num_elements; e++) {
                        of[i][j].x[e] += coef * fast_sigmoid(cf[i][j].x[e]);
                        cf[i][j].x[e] = 0.0f;
                    }
                }
        }
    }

    const float inv = __fdividef(1.0f, cum[ts - 1]);
    #pragma unroll
    for (int i = 0; i < 2; i++)
        #pragma unroll
        for (int j = 0; j < 4; j++) {
            #pragma unroll
            for (int e = 0; e < of[i][j].num_elements; e++)
                of[i][j].x[e] *= inv;
            const int mg = by * 128 + wm * 32 + i * 16;
            const int ng = bx * 128 + wn * 64 + j * 16;
            wmma::store_matrix_sync(out + (long)mg * NROWS + ng, of[i][j],
                                    NROWS, wmma::mem_row_major);
            if (bx != by)
                wmma::store_matrix_sync(out + (long)ng * NROWS + mg, of[i][j],
                                        NROWS, wmma::mem_col_major);
        }
}

// ---------------------------------------------------------------------------
// Pre/post-processing
// ---------------------------------------------------------------------------
__global__ void cvt_bf16_kernel(const float* __restrict__ src,
                                __nv_bfloat16* __restrict__ dst, long n8) {
    long i = (long)blockIdx.x * blockDim.x + threadIdx.x;
    long stride = (long)gridDim.x * blockDim.x;
    for (; i < n8; i += stride) {
        float4 va = reinterpret_cast<const float4*>(src)[2 * i];
        float4 vb = reinterpret_cast<const float4*>(src)[2 * i + 1];
        uint4 o;
        __nv_bfloat162 h0 = __floats2bfloat162_rn(va.x, va.y);
        __nv_bfloat162 h1 = __floats2bfloat162_rn(va.z, va.w);
        __nv_bfloat162 h2 = __floats2bfloat162_rn(vb.x, vb.y);
        __nv_bfloat162 h3 = __floats2bfloat162_rn(vb.z, vb.w);
        o.x = *reinterpret_cast<uint32_t*>(&h0);
        o.y = *reinterpret_cast<uint32_t*>(&h1);
        o.z = *reinterpret_cast<uint32_t*>(&h2);
        o.w = *reinterpret_cast<uint32_t*>(&h3);
        reinterpret_cast<uint4*>(dst)[i] = o;
    }
}
// Tiled X^T: Xt[n][k] = bf16(X[k][n]); coalesced reads and writes via smem.
__global__ void transpose_x_kernel(const float* __restrict__ X,
                                   __nv_bfloat16* __restrict__ Xt) {
    __shared__ float tile[32][33];
    const int tx = threadIdx.x & 31, ty = threadIdx.x >> 5;   // 32 x 8
    const int n0 = blockIdx.x * 32, k0 = blockIdx.y * 32;
    #pragma unroll
    for (int i = 0; i < 4; i++)
        tile[ty + 8 * i][tx] = X[(long)(k0 + ty + 8 * i) * DIN + n0 + tx];
    __syncthreads();
    #pragma unroll
    for (int i = 0; i < 4; i++)
        Xt[(long)(n0 + ty + 8 * i) * NROWS + k0 + tx] =
            __float2bfloat16(tile[tx][ty + 8 * i]);
}
// Merged W1/W2 slab transposes (y<NSTEP: W1 slab y; else W2 slab y-NSTEP)
__global__ void transpose_w2_kernel(const float* __restrict__ W1,
                                    const float* __restrict__ W2,
                                    __nv_bfloat16* __restrict__ W1t,
                                    __nv_bfloat16* __restrict__ W2t) {
    const int y = blockIdx.y;
    const float* Ws; __nv_bfloat16* Wd; int K, N;
    if (y < NSTEP) { Ws = W1 + (long)y * DIN * H1W; Wd = W1t + (long)y * DIN * H1W;
                     K = DIN; N = H1W; }
    else           { Ws = W2 + (long)(y - NSTEP) * H1W * H2W;
                     Wd = W2t + (long)(y - NSTEP) * H1W * H2W; K = H1W; N = H2W; }
    for (long idx = blockIdx.x * blockDim.x + threadIdx.x; idx < (long)K * N;
         idx += (long)gridDim.x * blockDim.x) {
        long n = idx / K, k = idx % K;
        Wd[n * K + k] = __float2bfloat16(Ws[k * N + n]);
    }
}
__global__ void mean_kernel(const float* __restrict__ H2, float* __restrict__ mean) {
    const int tx = threadIdx.x & 31;
    const int ty = threadIdx.x >> 5;
    const int col = blockIdx.x * 32 + tx;
    float s = 0.0f;
    for (int r = ty; r < NROWS; r += 8)
        s += H2[(long)r * N2 + col];
    __shared__ float red[8][32];
    red[ty][tx] = s;
    __syncthreads();
    if (ty == 0) {
        float t = 0.0f;
        #pragma unroll
        for (int i = 0; i < 8; i++) t += red[i][tx];
        mean[col] = t * (1.0f / NROWS);
    }
}
__global__ void center_kernel(const float* __restrict__ H2,
                              const float* __restrict__ mean,
                              __nv_bfloat16* __restrict__ a, long n) {
    long i = (long)blockIdx.x * blockDim.x + threadIdx.x;
    long st = (long)gridDim.x * blockDim.x;
    for (; i < n; i += st) {
        int c = (int)(i % N2);
        a[i] = __float2bfloat16(H2[i] - mean[c]);
    }
}

// ---------------------------------------------------------------------------
// Launch
// ---------------------------------------------------------------------------
extern "C" void kernel_launch(void* const* d_in, const int* in_sizes, int n_in,
                              void* d_out, int out_size) {
    const float* X   = (const float*)d_in[0];
    const float* adj = (const float*)d_in[1];
    const float* W1  = (const float*)d_in[2];
    const float* W2  = (const float*)d_in[3];
    const float* cum = (const float*)d_in[4];
    const float* som = (const float*)d_in[5];
    const int*   tsp = (const int*)d_in[6];
    const int*   Tp  = (const int*)d_in[7];
    float* out = (float*)d_out;
    (void)in_sizes; (void)n_in; (void)out_size;

    void *p_adjb, *p_xt, *p_ax, *p_w1t, *p_w2t, *p_h1, *p_t2t, *p_h2, *p_abf, *p_mean;
    cudaGetSymbolAddress(&p_adjb, g_adjb);
    cudaGetSymbolAddress(&p_xt,   g_Xt);
    cudaGetSymbolAddress(&p_ax,   g_AX);
    cudaGetSymbolAddress(&p_w1t,  g_W1t);
    cudaGetSymbolAddress(&p_w2t,  g_W2t);
    cudaGetSymbolAddress(&p_h1,   g_H1);
    cudaGetSymbolAddress(&p_t2t,  g_T2t);
    cudaGetSymbolAddress(&p_h2,   g_H2);
    cudaGetSymbolAddress(&p_abf,  g_abf);
    cudaGetSymbolAddress(&p_mean, g_mean);

    cudaFuncSetAttribute(wgemm<0>,   cudaFuncAttributeMaxDynamicSharedMemorySize, GSM);
    cudaFuncSetAttribute(wgemm<3>,   cudaFuncAttributeMaxDynamicSharedMemorySize, GSM);
    cudaFuncSetAttribute(wgemm64<1>, cudaFuncAttributeMaxDynamicSharedMemorySize, GSM64);
    cudaFuncSetAttribute(wgemm64<2>, cudaFuncAttributeMaxDynamicSharedMemorySize, GSM64);
    cudaFuncSetAttribute(wout,       cudaFuncAttributeMaxDynamicSharedMemorySize, GSM);

    // (1) adj -> bf16, (2) X^T tiled, (3) merged W transposes, (4) AX ← profiled
    cvt_bf16_kernel<<<4096, 256>>>(adj, (__nv_bfloat16*)p_adjb, (long)NROWS * NROWS / 8);
    transpose_x_kernel<<<dim3(DIN/32, NROWS/32), 256>>>(X, (__nv_bfloat16*)p_xt);
    transpose_w2_kernel<<<dim3(48, 2 * NSTEP), 256>>>(
        W1 + (size_t)DIN * H1W, W2 + (size_t)H1W * H2W,
        (__nv_bfloat16*)p_w1t, (__nv_bfloat16*)p_w2t);

    // AX = adj @ X                 [8192 x 512] bf16 (no relu)
    wgemm<3><<<dim3(DIN/128, NROWS/128), 128, GSM>>>(
        (const __nv_bfloat16*)p_adjb, NROWS, 0,
        (const __nv_bfloat16*)p_xt, NROWS, 0, DIN,
        (char*)p_ax, DIN, NROWS);

    // H1 = relu(AX @ W1slab)  [8192 x 1280] bf16 — 64-row tiles (tail fix)
    wgemm64<1><<<dim3(N1/128, NROWS/64), 128, GSM64>>>(
        (const __nv_bfloat16*)p_ax, DIN,
        (const __nv_bfloat16*)p_w1t, DIN, (long)H1W * DIN, H1W,
        (char*)p_h1, N1, DIN);

    // T2t = (H1slab @ W2slab)^T    [640 x 8192] bf16
    wgemm<0><<<dim3(N2/128, NROWS/128), 128, GSM>>>(
        (const __nv_bfloat16*)p_h1, N1, H1W,
        (const __nv_bfloat16*)p_w2t, H1W, (long)H2W * H1W, H2W,
        (char*)p_t2t, NROWS, H1W);

    // H2 = relu(adj @ T2)  [8192 x 640] f32 — 64-row tiles, 2-stage, 4 CTAs/SM
    wgemm64<2><<<dim3(N2/128, NROWS/64), 128, GSM64>>>(
        (const __nv_bfloat16*)p_adjb, NROWS,
        (const __nv_bfloat16*)p_t2t, NROWS, 0, N2,
        (char*)p_h2, N2, NROWS);

    mean_kernel<<<N2 / 32, 256>>>((const float*)p_h2, (float*)p_mean);
    center_kernel<<<4096, 256>>>((const float*)p_h2, (const float*)p_mean,
                                 (__nv_bfloat16*)p_abf, (long)NROWS * N2);

    wout<<<dim3(NROWS/128, NROWS/128), 256, GSM>>>(
        (const __nv_bfloat16*)p_abf, som, cum, tsp, Tp, out);
}